// round 6
// baseline (speedup 1.0000x reference)
#include <cuda_runtime.h>
#include <cuda_bf16.h>
#include <cstdint>

// ---------------------------------------------------------------------------
// FeatherNet via warp-level mma.sync tf32 (generic PTX):
//   Vf = V1@V2 ; h1 = relu(x W1^T + b1); h2 = relu(h1 W2^T + b2); out = h2 W3^T + b3
// All 4 GEMMs NT: C[M,N] = A[M,K] * B[N,K]^T.
// R6: CTA 128x256, 8 warps (2Mx4N) of 64x64, 3-stage ring, 1 CTA/SM.
//     Halves cp.async issue per MMA (LSU was the binding pipe).
// ---------------------------------------------------------------------------

#define SIZE_N 5794
#define SIZE_M 2897
#define K_PAD  2912        // 91 * 32
#define BATCH  4096
#define D_IN   2048
#define D_H    4096
#define D_OUT  2048

#define OFF_W1 0
#define OFF_B1 8388608
#define OFF_B2 25169920
#define OFF_W2 8392704
#define OFF_W3 25174016
#define OFF_B3 33562624

__device__ __align__(256) float g_V1r[(size_t)SIZE_N * K_PAD];
__device__ __align__(256) float g_V2T[(size_t)SIZE_N * K_PAD];
__device__ __align__(256) float g_xr [(size_t)BATCH * D_IN];
__device__ __align__(256) float g_Vf [(size_t)SIZE_N * SIZE_N];
__device__ __align__(256) float g_h1 [(size_t)BATCH * D_H];
__device__ __align__(256) float g_h2 [(size_t)BATCH * D_H];

// ============================ helpers =======================================

__device__ __forceinline__ float rna_tf32(float v) {
    uint32_t u;
    asm("cvt.rna.tf32.f32 %0, %1;" : "=r"(u) : "f"(v));
    return __uint_as_float(u);
}

__device__ __forceinline__ uint32_t smem_u32(const void* p) {
    uint32_t a;
    asm("{ .reg .u64 t; cvta.to.shared.u64 t, %1; cvt.u32.u64 %0, t; }"
        : "=r"(a) : "l"(p));
    return a;
}

__device__ __forceinline__ void cp_async16(uint32_t dst, const void* src, bool valid) {
    int sz = valid ? 16 : 0;
    asm volatile("cp.async.cg.shared.global [%0], [%1], 16, %2;"
                 :: "r"(dst), "l"(src), "r"(sz) : "memory");
}
#define CP_COMMIT()  asm volatile("cp.async.commit_group;" ::: "memory")
#define CP_WAIT_1()  asm volatile("cp.async.wait_group 1;" ::: "memory")

__device__ __forceinline__ void mma_tf32(float4& d, const uint32_t* a, const uint32_t* b) {
    asm volatile(
        "mma.sync.aligned.m16n8k8.row.col.f32.tf32.tf32.f32 "
        "{%0,%1,%2,%3}, {%4,%5,%6,%7}, {%8,%9}, {%0,%1,%2,%3};"
        : "+f"(d.x), "+f"(d.y), "+f"(d.z), "+f"(d.w)
        : "r"(a[0]), "r"(a[1]), "r"(a[2]), "r"(a[3]), "r"(b[0]), "r"(b[1]));
}

// smem: tile rows of 32 floats (128B), 16B groups XOR-swizzled by row.
__device__ __forceinline__ int sw(int row, int k) {
    return row * 32 + ((((k >> 2) ^ row) & 7) << 2) + (k & 3);
}

// ============================ GEMM kernel ===================================
// CTA tile 128(M) x 256(N), BK=32, 8 warps (2M x 4N), warp tile 64x64.

#define A_TILE_F 4096          // 128 * 32 floats
#define B_TILE_F 8192          // 256 * 32 floats
#define STAGE_F  12288         // A + B
#define NST      3
#define SMEM_BYTES (NST * STAGE_F * 4)   // 147456

template<bool BIAS, bool RELU, bool ROUND>
__global__ __launch_bounds__(256, 1)
void gemm_mma(const float* __restrict__ A, const float* __restrict__ B,
              const float* __restrict__ bias, float* __restrict__ C,
              int M, int N, int K, int lda, int ldb, int ldc)
{
    extern __shared__ float smf[];
    const uint32_t smem_base = smem_u32(smf);

    const int tid = threadIdx.x;
    const int wid = tid >> 5;
    const int lid = tid & 31;
    const int r   = lid >> 2;     // 0..7
    const int c   = lid & 3;      // 0..3
    const int bm  = blockIdx.y * 128;
    const int bn  = blockIdx.x * 256;
    const int m0  = (wid & 1) * 64;
    const int n0  = (wid >> 1) * 64;   // 0,64,128,192

    float4 acc[4][8];
#pragma unroll
    for (int i = 0; i < 4; i++)
#pragma unroll
        for (int j = 0; j < 8; j++) acc[i][j] = make_float4(0.f, 0.f, 0.f, 0.f);

    const int T = K >> 5;   // K / 32

    auto load_stage = [&](int t, int buf) {
        const int kblk = t * 32;
        uint32_t sA = smem_base + (uint32_t)(buf * STAGE_F) * 4;
        uint32_t sB = sA + A_TILE_F * 4;
        // A: 128 rows x 8 groups = 1024 chunks, 4 per thread
#pragma unroll
        for (int i = 0; i < 4; i++) {
            int q = tid + i * 256;
            int row = q >> 3, cg = q & 7;
            int gm = bm + row;
            bool v = gm < M;
            const float* src = A + (size_t)(v ? gm : 0) * lda + kblk + cg * 4;
            cp_async16(sA + (uint32_t)(sw(row, cg * 4)) * 4, src, v);
        }
        // B: 256 rows x 8 groups = 2048 chunks, 8 per thread
#pragma unroll
        for (int i = 0; i < 8; i++) {
            int q = tid + i * 256;
            int row = q >> 3, cg = q & 7;
            int gn = bn + row;
            bool v = gn < N;
            const float* src = B + (size_t)(v ? gn : 0) * ldb + kblk + cg * 4;
            cp_async16(sB + (uint32_t)(sw(row, cg * 4)) * 4, src, v);
        }
        CP_COMMIT();
    };

    load_stage(0, 0);
    if (T > 1) load_stage(1, 1); else CP_COMMIT();

    int buf = 0;
    for (int t = 0; t < T; t++) {
        CP_WAIT_1();
        __syncthreads();

        if (t + 2 < T) load_stage(t + 2, (t + 2) % NST);
        else CP_COMMIT();

        const float* As = smf + buf * STAGE_F;
        const float* Bs = As + A_TILE_F;
        const uint32_t* Asu = (const uint32_t*)As;
        const uint32_t* Bsu = (const uint32_t*)Bs;

#pragma unroll
        for (int kc = 0; kc < 4; kc++) {
            const int k0 = kc * 8;
            uint32_t af[4][4], bf[8][2];
#pragma unroll
            for (int i = 0; i < 4; i++) {
                int R = m0 + i * 16 + r;
                af[i][0] = Asu[sw(R,     k0 + c)];
                af[i][1] = Asu[sw(R + 8, k0 + c)];
                af[i][2] = Asu[sw(R,     k0 + c + 4)];
                af[i][3] = Asu[sw(R + 8, k0 + c + 4)];
            }
#pragma unroll
            for (int j = 0; j < 8; j++) {
                int Rb = n0 + j * 8 + r;
                bf[j][0] = Bsu[sw(Rb, k0 + c)];
                bf[j][1] = Bsu[sw(Rb, k0 + c + 4)];
            }
#pragma unroll
            for (int i = 0; i < 4; i++)
#pragma unroll
                for (int j = 0; j < 8; j++)
                    mma_tf32(acc[i][j], af[i], bf[j]);
        }

        buf++;
        if (buf == NST) buf = 0;
    }

    // ---- epilogue ----------------------------------------------------------
#pragma unroll
    for (int i = 0; i < 4; i++) {
        int gm0 = bm + m0 + i * 16 + r;
#pragma unroll
        for (int j = 0; j < 8; j++) {
            int gn = bn + n0 + j * 8 + 2 * c;
            if (gn >= N) continue;
            float b0 = 0.f, b1 = 0.f;
            if (BIAS) { b0 = __ldg(&bias[gn]); b1 = __ldg(&bias[gn + 1]); }
            float4 v = acc[i][j];
            float x0 = v.x + b0, x1 = v.y + b1;
            float y0 = v.z + b0, y1 = v.w + b1;
            if (RELU) {
                x0 = fmaxf(x0, 0.f); x1 = fmaxf(x1, 0.f);
                y0 = fmaxf(y0, 0.f); y1 = fmaxf(y1, 0.f);
            }
            if (ROUND) {
                x0 = rna_tf32(x0); x1 = rna_tf32(x1);
                y0 = rna_tf32(y0); y1 = rna_tf32(y1);
            }
            if (gm0 < M)
                *(float2*)(&C[(size_t)gm0 * ldc + gn]) = make_float2(x0, x1);
            if (gm0 + 8 < M)
                *(float2*)(&C[(size_t)(gm0 + 8) * ldc + gn]) = make_float2(y0, y1);
        }
    }
}

// ============================ prep kernels ==================================

__global__ void round_pad_kernel(const float* __restrict__ src, float* __restrict__ dst,
                                 int rows, int cols, int dstride)
{
    int total = rows * dstride;
    for (int i = blockIdx.x * blockDim.x + threadIdx.x; i < total; i += gridDim.x * blockDim.x) {
        int rr = i / dstride, cc = i - rr * dstride;
        float v = 0.0f;
        if (cc < cols) v = rna_tf32(src[(size_t)rr * cols + cc]);
        dst[i] = v;
    }
}

__global__ void transpose_round_kernel(const float* __restrict__ src, float* __restrict__ dst)
{
    __shared__ float t[32][33];
    int nb = blockIdx.x * 32;
    int kb = blockIdx.y * 32;
    int x = threadIdx.x, y = threadIdx.y;   // 32 x 8
#pragma unroll
    for (int yy = y; yy < 32; yy += 8) {
        int k = kb + yy, n = nb + x;
        float v = 0.0f;
        if (k < SIZE_M && n < SIZE_N) v = rna_tf32(src[(size_t)k * SIZE_N + n]);
        t[yy][x] = v;
    }
    __syncthreads();
#pragma unroll
    for (int yy = y; yy < 32; yy += 8) {
        int n = nb + yy, k = kb + x;
        if (n < SIZE_N && k < K_PAD) dst[(size_t)n * K_PAD + k] = t[x][yy];
    }
}

// ============================ host side =====================================

static inline dim3 grid_for(int M, int N) {
    return dim3((N + 255) / 256, (M + 127) / 128);
}

extern "C" void kernel_launch(void* const* d_in, const int* in_sizes, int n_in,
                              void* d_out, int out_size)
{
    const float* x  = (const float*)d_in[0];   // [4096, 2048]
    const float* V1 = (const float*)d_in[1];   // [5794, 2897]
    const float* V2 = (const float*)d_in[2];   // [2897, 5794]
    float* out = (float*)d_out;                // [4096, 2048]

    float *V1r, *V2T, *xr, *Vf, *h1, *h2;
    cudaGetSymbolAddress((void**)&V1r, g_V1r);
    cudaGetSymbolAddress((void**)&V2T, g_V2T);
    cudaGetSymbolAddress((void**)&xr,  g_xr);
    cudaGetSymbolAddress((void**)&Vf,  g_Vf);
    cudaGetSymbolAddress((void**)&h1,  g_h1);
    cudaGetSymbolAddress((void**)&h2,  g_h2);

    round_pad_kernel<<<2048, 256>>>(V1, V1r, SIZE_N, SIZE_M, K_PAD);
    round_pad_kernel<<<2048, 256>>>(x, xr, BATCH, D_IN, D_IN);
    transpose_round_kernel<<<dim3((SIZE_N + 31) / 32, (K_PAD + 31) / 32), dim3(32, 8)>>>(V2, V2T);

    cudaFuncSetAttribute(gemm_mma<false, false, true>,
                         cudaFuncAttributeMaxDynamicSharedMemorySize, SMEM_BYTES);
    cudaFuncSetAttribute(gemm_mma<true, true, true>,
                         cudaFuncAttributeMaxDynamicSharedMemorySize, SMEM_BYTES);
    cudaFuncSetAttribute(gemm_mma<true, false, false>,
                         cudaFuncAttributeMaxDynamicSharedMemorySize, SMEM_BYTES);

    // 1) Vf = V1r @ V2T^T
    gemm_mma<false, false, true><<<grid_for(SIZE_N, SIZE_N), 256, SMEM_BYTES>>>(
        V1r, V2T, nullptr, Vf, SIZE_N, SIZE_N, K_PAD, K_PAD, K_PAD, SIZE_N);

    // 2) h1 = relu(xr @ W1^T + b1)
    gemm_mma<true, true, true><<<grid_for(BATCH, D_H), 256, SMEM_BYTES>>>(
        xr, Vf + OFF_W1, Vf + OFF_B1, h1, BATCH, D_H, D_IN, D_IN, D_IN, D_H);

    // 3) h2 = relu(h1 @ W2^T + b2)
    gemm_mma<true, true, true><<<grid_for(BATCH, D_H), 256, SMEM_BYTES>>>(
        h1, Vf + OFF_W2, Vf + OFF_B2, h2, BATCH, D_H, D_H, D_H, D_H, D_H);

    // 4) out = h2 @ W3^T + b3
    gemm_mma<true, false, false><<<grid_for(BATCH, D_OUT), 256, SMEM_BYTES>>>(
        h2, Vf + OFF_W3, Vf + OFF_B3, out, BATCH, D_OUT, D_H, D_H, D_H, D_OUT);
}

// round 7
// speedup vs baseline: 2.0673x; 2.0673x over previous
#include <cuda_runtime.h>
#include <cuda_fp16.h>
#include <cstdint>

// ---------------------------------------------------------------------------
// FeatherNet via warp-level mma.sync fp16 (m16n8k16, fp32 accum):
//   Vf = V1@V2 ; h1 = relu(x W1^T + b1); h2 = relu(h1 W2^T + b2); out = h2 W3^T + b3
// All 4 GEMMs NT: C[M,N] = A[M,K] * B[N,K]^T. Operands fp16 (10-bit mantissa,
// same as tf32), accumulate fp32, intermediates stored fp16, output fp32.
// R7: R5's winning shape (128x128 CTA, 4 warps 64x64, 3-stage ring, 2 CTA/SM)
//     with 2x tensor throughput via fp16 k16 MMA.
// ---------------------------------------------------------------------------

#define SIZE_N 5794
#define SIZE_M 2897
#define K_PAD  2944        // 46 * 64 (BK=64 halves)
#define BATCH  4096
#define D_IN   2048
#define D_H    4096
#define D_OUT  2048

#define OFF_W1 0
#define OFF_B1 8388608
#define OFF_W2 8392704
#define OFF_B2 25169920
#define OFF_W3 25174016
#define OFF_B3 33562624

__device__ __align__(256) __half g_V1h[(size_t)SIZE_N * K_PAD];
__device__ __align__(256) __half g_V2T[(size_t)SIZE_N * K_PAD];
__device__ __align__(256) __half g_xh [(size_t)BATCH * D_IN];
__device__ __align__(256) __half g_Vf [(size_t)SIZE_N * SIZE_N];
__device__ __align__(256) __half g_h1 [(size_t)BATCH * D_H];
__device__ __align__(256) __half g_h2 [(size_t)BATCH * D_H];

// ============================ helpers =======================================

__device__ __forceinline__ uint32_t smem_u32(const void* p) {
    uint32_t a;
    asm("{ .reg .u64 t; cvta.to.shared.u64 t, %1; cvt.u32.u64 %0, t; }"
        : "=r"(a) : "l"(p));
    return a;
}

__device__ __forceinline__ void cp_async16(uint32_t dst, const void* src, bool valid) {
    int sz = valid ? 16 : 0;
    asm volatile("cp.async.cg.shared.global [%0], [%1], 16, %2;"
                 :: "r"(dst), "l"(src), "r"(sz) : "memory");
}
#define CP_COMMIT()  asm volatile("cp.async.commit_group;" ::: "memory")
#define CP_WAIT_1()  asm volatile("cp.async.wait_group 1;" ::: "memory")

__device__ __forceinline__ void mma_f16(float4& d, const uint32_t* a, const uint32_t* b) {
    asm volatile(
        "mma.sync.aligned.m16n8k16.row.col.f32.f16.f16.f32 "
        "{%0,%1,%2,%3}, {%4,%5,%6,%7}, {%8,%9}, {%0,%1,%2,%3};"
        : "+f"(d.x), "+f"(d.y), "+f"(d.z), "+f"(d.w)
        : "r"(a[0]), "r"(a[1]), "r"(a[2]), "r"(a[3]), "r"(b[0]), "r"(b[1]));
}

// smem: tile rows of 32 uint32 (=64 halves = 128B), 16B groups XOR-swizzled.
// k is in uint32 (half2) units, 0..31.
__device__ __forceinline__ int sw(int row, int k) {
    return row * 32 + ((((k >> 2) ^ row) & 7) << 2) + (k & 3);
}

// ============================ GEMM kernel ===================================
// 128x128 CTA tile, BK=64 halves, 4 warps (2M x 2N), warp tile 64x64, 3-stage.

#define A_TILE_U 4096          // 128 rows * 32 u32
#define STAGE_U  8192          // A + B (32KB)
#define NST      3
#define SMEM_BYTES (NST * STAGE_U * 4)   // 98304

template<bool BIAS, bool RELU, typename CT>
__global__ __launch_bounds__(128, 2)
void gemm_mma(const __half* __restrict__ A, const __half* __restrict__ B,
              const __half* __restrict__ bias, CT* __restrict__ C,
              int M, int N, int K, int lda, int ldb, int ldc)
{
    extern __shared__ uint32_t smu[];
    const uint32_t smem_base = smem_u32(smu);

    const int tid = threadIdx.x;
    const int wid = tid >> 5;
    const int lid = tid & 31;
    const int r   = lid >> 2;     // 0..7  (groupID)
    const int c   = lid & 3;      // 0..3  (threadID in group)
    const int bm  = blockIdx.y * 128;
    const int bn  = blockIdx.x * 128;
    const int m0  = (wid & 1) * 64;
    const int n0  = (wid >> 1) * 64;

    float4 acc[4][8];
#pragma unroll
    for (int i = 0; i < 4; i++)
#pragma unroll
        for (int j = 0; j < 8; j++) acc[i][j] = make_float4(0.f, 0.f, 0.f, 0.f);

    const int T = K >> 6;   // K / 64

    // per stage: A 128 rows x 8 chunks(16B) + B same = 2048 chunks, 16/thread
    auto load_stage = [&](int t, int buf) {
        const int kblk = t * 64;   // in halves
        uint32_t sA = smem_base + (uint32_t)(buf * STAGE_U) * 4;
        uint32_t sB = sA + A_TILE_U * 4;
#pragma unroll
        for (int i = 0; i < 8; i++) {
            int q = tid + i * 128;
            int row = q >> 3, cg = q & 7;
            int gm = bm + row;
            bool v = gm < M;
            const __half* src = A + (size_t)(v ? gm : 0) * lda + kblk + cg * 8;
            cp_async16(sA + (uint32_t)(sw(row, cg * 4)) * 4, src, v);
        }
#pragma unroll
        for (int i = 0; i < 8; i++) {
            int q = tid + i * 128;
            int row = q >> 3, cg = q & 7;
            int gn = bn + row;
            bool v = gn < N;
            const __half* src = B + (size_t)(v ? gn : 0) * ldb + kblk + cg * 8;
            cp_async16(sB + (uint32_t)(sw(row, cg * 4)) * 4, src, v);
        }
        CP_COMMIT();
    };

    load_stage(0, 0);
    if (T > 1) load_stage(1, 1); else CP_COMMIT();

    int buf = 0;
    for (int t = 0; t < T; t++) {
        CP_WAIT_1();
        __syncthreads();

        if (t + 2 < T) load_stage(t + 2, (t + 2) % NST);
        else CP_COMMIT();

        const uint32_t* Asu = smu + buf * STAGE_U;
        const uint32_t* Bsu = Asu + A_TILE_U;

        // 4 k16-groups per stage; u32 k-offset k0 = kc*8
#pragma unroll
        for (int kc = 0; kc < 4; kc++) {
            const int k0 = kc * 8;
            uint32_t af[4][4], bf[8][2];
#pragma unroll
            for (int i = 0; i < 4; i++) {
                int R = m0 + i * 16 + r;
                af[i][0] = Asu[sw(R,     k0 + c)];
                af[i][1] = Asu[sw(R + 8, k0 + c)];
                af[i][2] = Asu[sw(R,     k0 + c + 4)];
                af[i][3] = Asu[sw(R + 8, k0 + c + 4)];
            }
#pragma unroll
            for (int j = 0; j < 8; j++) {
                int Rb = n0 + j * 8 + r;
                bf[j][0] = Bsu[sw(Rb, k0 + c)];
                bf[j][1] = Bsu[sw(Rb, k0 + c + 4)];
            }
#pragma unroll
            for (int i = 0; i < 4; i++)
#pragma unroll
                for (int j = 0; j < 8; j++)
                    mma_f16(acc[i][j], af[i], bf[j]);
        }

        buf++;
        if (buf == NST) buf = 0;
    }

    // ---- epilogue: bias + relu; store half2 (intermediates) or float2 ------
#pragma unroll
    for (int i = 0; i < 4; i++) {
        int gm0 = bm + m0 + i * 16 + r;
#pragma unroll
        for (int j = 0; j < 8; j++) {
            int gn = bn + n0 + j * 8 + 2 * c;
            if (gn >= N) continue;
            float b0 = 0.f, b1 = 0.f;
            if (BIAS) {
                b0 = __half2float(__ldg(&bias[gn]));
                b1 = __half2float(__ldg(&bias[gn + 1]));
            }
            float4 v = acc[i][j];
            float x0 = v.x + b0, x1 = v.y + b1;
            float y0 = v.z + b0, y1 = v.w + b1;
            if (RELU) {
                x0 = fmaxf(x0, 0.f); x1 = fmaxf(x1, 0.f);
                y0 = fmaxf(y0, 0.f); y1 = fmaxf(y1, 0.f);
            }
            if (gm0 < M) {
                CT* p = &C[(size_t)gm0 * ldc + gn];
                if (sizeof(CT) == 2) *(half2*)p = __floats2half2_rn(x0, x1);
                else                 *(float2*)p = make_float2(x0, x1);
            }
            if (gm0 + 8 < M) {
                CT* p = &C[(size_t)(gm0 + 8) * ldc + gn];
                if (sizeof(CT) == 2) *(half2*)p = __floats2half2_rn(y0, y1);
                else                 *(float2*)p = make_float2(y0, y1);
            }
        }
    }
}

// ============================ prep kernels ==================================

// dst[r*dstride + c] = half(src[r*cols + c]) for c<cols, else 0
__global__ void tohalf_pad_kernel(const float* __restrict__ src, __half* __restrict__ dst,
                                  int rows, int cols, int dstride)
{
    int total = rows * dstride;
    for (int i = blockIdx.x * blockDim.x + threadIdx.x; i < total; i += gridDim.x * blockDim.x) {
        int rr = i / dstride, cc = i - rr * dstride;
        float v = 0.0f;
        if (cc < cols) v = src[(size_t)rr * cols + cc];
        dst[i] = __float2half_rn(v);
    }
}

// V2 [SIZE_M x SIZE_N] f32 -> V2T [SIZE_N x K_PAD] f16, zero-padded K
__global__ void transpose_half_kernel(const float* __restrict__ src, __half* __restrict__ dst)
{
    __shared__ float t[32][33];
    int nb = blockIdx.x * 32;
    int kb = blockIdx.y * 32;
    int x = threadIdx.x, y = threadIdx.y;   // 32 x 8
#pragma unroll
    for (int yy = y; yy < 32; yy += 8) {
        int k = kb + yy, n = nb + x;
        float v = 0.0f;
        if (k < SIZE_M && n < SIZE_N) v = src[(size_t)k * SIZE_N + n];
        t[yy][x] = v;
    }
    __syncthreads();
#pragma unroll
    for (int yy = y; yy < 32; yy += 8) {
        int n = nb + yy, k = kb + x;
        if (n < SIZE_N && k < K_PAD) dst[(size_t)n * K_PAD + k] = __float2half_rn(t[x][yy]);
    }
}

// ============================ host side =====================================

static inline dim3 grid_for(int M, int N) {
    return dim3((N + 127) / 128, (M + 127) / 128);
}

extern "C" void kernel_launch(void* const* d_in, const int* in_sizes, int n_in,
                              void* d_out, int out_size)
{
    const float* x  = (const float*)d_in[0];   // [4096, 2048]
    const float* V1 = (const float*)d_in[1];   // [5794, 2897]
    const float* V2 = (const float*)d_in[2];   // [2897, 5794]
    float* out = (float*)d_out;                // [4096, 2048]

    __half *V1h, *V2T, *xh, *Vf, *h1, *h2;
    cudaGetSymbolAddress((void**)&V1h, g_V1h);
    cudaGetSymbolAddress((void**)&V2T, g_V2T);
    cudaGetSymbolAddress((void**)&xh,  g_xh);
    cudaGetSymbolAddress((void**)&Vf,  g_Vf);
    cudaGetSymbolAddress((void**)&h1,  g_h1);
    cudaGetSymbolAddress((void**)&h2,  g_h2);

    tohalf_pad_kernel<<<2048, 256>>>(V1, V1h, SIZE_N, SIZE_M, K_PAD);
    tohalf_pad_kernel<<<2048, 256>>>(x, xh, BATCH, D_IN, D_IN);
    transpose_half_kernel<<<dim3((SIZE_N + 31) / 32, (K_PAD + 31) / 32), dim3(32, 8)>>>(V2, V2T);

    cudaFuncSetAttribute(gemm_mma<false, false, __half>,
                         cudaFuncAttributeMaxDynamicSharedMemorySize, SMEM_BYTES);
    cudaFuncSetAttribute(gemm_mma<true, true, __half>,
                         cudaFuncAttributeMaxDynamicSharedMemorySize, SMEM_BYTES);
    cudaFuncSetAttribute(gemm_mma<true, false, float>,
                         cudaFuncAttributeMaxDynamicSharedMemorySize, SMEM_BYTES);

    // 1) Vf = V1h @ V2T^T   (half out), K padded to 2944
    gemm_mma<false, false, __half><<<grid_for(SIZE_N, SIZE_N), 128, SMEM_BYTES>>>(
        V1h, V2T, nullptr, Vf, SIZE_N, SIZE_N, K_PAD, K_PAD, K_PAD, SIZE_N);

    // 2) h1 = relu(xh @ W1^T + b1)  (half out)
    gemm_mma<true, true, __half><<<grid_for(BATCH, D_H), 128, SMEM_BYTES>>>(
        xh, Vf + OFF_W1, Vf + OFF_B1, h1, BATCH, D_H, D_IN, D_IN, D_IN, D_H);

    // 3) h2 = relu(h1 @ W2^T + b2)  (half out)
    gemm_mma<true, true, __half><<<grid_for(BATCH, D_H), 128, SMEM_BYTES>>>(
        h1, Vf + OFF_W2, Vf + OFF_B2, h2, BATCH, D_H, D_H, D_H, D_H, D_H);

    // 4) out = h2 @ W3^T + b3  (float out)
    gemm_mma<true, false, float><<<grid_for(BATCH, D_OUT), 128, SMEM_BYTES>>>(
        h2, Vf + OFF_W3, Vf + OFF_B3, out, BATCH, D_OUT, D_H, D_H, D_H, D_OUT);
}

// round 8
// speedup vs baseline: 2.1587x; 1.0442x over previous
#include <cuda_runtime.h>
#include <cuda_fp16.h>
#include <cstdint>

// ---------------------------------------------------------------------------
// FeatherNet via warp-level mma.sync fp16 (m16n8k16, fp32 accum):
//   Vf = V1@V2 ; h1 = relu(x W1^T + b1); h2 = relu(h1 W2^T + b2); out = h2 W3^T + b3
// All 4 GEMMs NT. R8: ldmatrix.x4 fragment loads (4x fewer ld instrs) +
// kc+1 fragment double-buffering. Shape = R5/R7 winner: 128x128 CTA,
// 4 warps 64x64, BK=64 halves, 3-stage cp.async ring, 2 CTA/SM.
// ---------------------------------------------------------------------------

#define SIZE_N 5794
#define SIZE_M 2897
#define K_PAD  2944        // 46 * 64
#define BATCH  4096
#define D_IN   2048
#define D_H    4096
#define D_OUT  2048

#define OFF_W1 0
#define OFF_B1 8388608
#define OFF_W2 8392704
#define OFF_B2 25169920
#define OFF_W3 25174016
#define OFF_B3 33562624

__device__ __align__(256) __half g_V1h[(size_t)SIZE_N * K_PAD];
__device__ __align__(256) __half g_V2T[(size_t)SIZE_N * K_PAD];
__device__ __align__(256) __half g_xh [(size_t)BATCH * D_IN];
__device__ __align__(256) __half g_Vf [(size_t)SIZE_N * SIZE_N];
__device__ __align__(256) __half g_h1 [(size_t)BATCH * D_H];
__device__ __align__(256) __half g_h2 [(size_t)BATCH * D_H];

// ============================ helpers =======================================

__device__ __forceinline__ uint32_t smem_u32(const void* p) {
    uint32_t a;
    asm("{ .reg .u64 t; cvta.to.shared.u64 t, %1; cvt.u32.u64 %0, t; }"
        : "=r"(a) : "l"(p));
    return a;
}

__device__ __forceinline__ void cp_async16(uint32_t dst, const void* src, bool valid) {
    int sz = valid ? 16 : 0;
    asm volatile("cp.async.cg.shared.global [%0], [%1], 16, %2;"
                 :: "r"(dst), "l"(src), "r"(sz) : "memory");
}
#define CP_COMMIT()  asm volatile("cp.async.commit_group;" ::: "memory")
#define CP_WAIT_1()  asm volatile("cp.async.wait_group 1;" ::: "memory")

__device__ __forceinline__ void mma_f16(float4& d, const uint32_t* a, const uint32_t* b) {
    asm volatile(
        "mma.sync.aligned.m16n8k16.row.col.f32.f16.f16.f32 "
        "{%0,%1,%2,%3}, {%4,%5,%6,%7}, {%8,%9}, {%0,%1,%2,%3};"
        : "+f"(d.x), "+f"(d.y), "+f"(d.z), "+f"(d.w)
        : "r"(a[0]), "r"(a[1]), "r"(a[2]), "r"(a[3]), "r"(b[0]), "r"(b[1]));
}

__device__ __forceinline__ void ldsm_x4(uint32_t* r, uint32_t addr) {
    asm volatile("ldmatrix.sync.aligned.m8n8.x4.shared.b16 {%0,%1,%2,%3}, [%4];"
                 : "=r"(r[0]), "=r"(r[1]), "=r"(r[2]), "=r"(r[3]) : "r"(addr));
}

// smem: tile rows of 32 u32 (=64 halves = 128B), 16B groups XOR-swizzled by row.
__device__ __forceinline__ int sw(int row, int k) {
    return row * 32 + ((((k >> 2) ^ row) & 7) << 2) + (k & 3);
}

// ============================ GEMM kernel ===================================

#define A_TILE_U 4096          // 128 rows * 32 u32
#define STAGE_U  8192          // A + B (32KB)
#define NST      3
#define SMEM_BYTES (NST * STAGE_U * 4)   // 98304

template<bool BIAS, bool RELU, typename CT>
__global__ __launch_bounds__(128, 2)
void gemm_mma(const __half* __restrict__ A, const __half* __restrict__ B,
              const __half* __restrict__ bias, CT* __restrict__ C,
              int M, int N, int K, int lda, int ldb, int ldc)
{
    extern __shared__ uint32_t smu[];
    const uint32_t smem_base = smem_u32(smu);

    const int tid = threadIdx.x;
    const int wid = tid >> 5;
    const int lid = tid & 31;
    const int r   = lid >> 2;
    const int c   = lid & 3;
    const int bm  = blockIdx.y * 128;
    const int bn  = blockIdx.x * 128;
    const int m0  = (wid & 1) * 64;
    const int n0  = (wid >> 1) * 64;

    // ---- ldmatrix per-lane address constants --------------------------------
    // A x4 for tile i: mats {(+0,g),( +8,g),(+0,g+1),(+8,g+1)}, g = 2*kc
    // lane l: row = m0 + i*16 + ((l>>3)&1)*8 + (l&7); 16B-group = 2kc + (l>>4)
    // B x4 for j-pair jp: mats {(j0,g),(j0,g+1),(j0+1,g),(j0+1,g+1)}, j0=2jp
    // lane l: row = n0 + (2jp + (l>>4))*8 + (l&7); group = 2kc + ((l>>3)&1)
    // row&7 == l&7 always (all row offsets are multiples of 8).
    const int e    = lid & 7;
    const uint32_t aRowB = (uint32_t)(m0 + ((lid >> 3) & 1) * 8 + e) * 128;
    const uint32_t bRowB = (uint32_t)(n0 + (lid >> 4) * 8 + e) * 128;
    uint32_t xa[4], xb[4];
#pragma unroll
    for (int kc = 0; kc < 4; kc++) {
        xa[kc] = (uint32_t)((((2 * kc + (lid >> 4)) ^ e) & 7) * 16);
        xb[kc] = (uint32_t)((((2 * kc + ((lid >> 3) & 1)) ^ e) & 7) * 16);
    }

    float4 acc[4][8];
#pragma unroll
    for (int i = 0; i < 4; i++)
#pragma unroll
        for (int j = 0; j < 8; j++) acc[i][j] = make_float4(0.f, 0.f, 0.f, 0.f);

    const int T = K >> 6;   // K / 64

    auto load_stage = [&](int t, int buf) {
        const int kblk = t * 64;   // halves
        uint32_t sA = smem_base + (uint32_t)(buf * STAGE_U) * 4;
        uint32_t sB = sA + A_TILE_U * 4;
#pragma unroll
        for (int i = 0; i < 8; i++) {
            int q = tid + i * 128;
            int row = q >> 3, cg = q & 7;
            int gm = bm + row;
            bool v = gm < M;
            const __half* src = A + (size_t)(v ? gm : 0) * lda + kblk + cg * 8;
            cp_async16(sA + (uint32_t)(sw(row, cg * 4)) * 4, src, v);
        }
#pragma unroll
        for (int i = 0; i < 8; i++) {
            int q = tid + i * 128;
            int row = q >> 3, cg = q & 7;
            int gn = bn + row;
            bool v = gn < N;
            const __half* src = B + (size_t)(v ? gn : 0) * ldb + kblk + cg * 8;
            cp_async16(sB + (uint32_t)(sw(row, cg * 4)) * 4, src, v);
        }
        CP_COMMIT();
    };

    load_stage(0, 0);
    if (T > 1) load_stage(1, 1); else CP_COMMIT();

    // fragment double buffers: fa[pb][i][0..3], fb[pb][jp][0..3]
    // fb[pb][jp] = { b0(j=2jp), b1(j=2jp), b0(j=2jp+1), b1(j=2jp+1) }
    uint32_t fa[2][4][4], fb[2][4][4];

    int buf = 0;
    for (int t = 0; t < T; t++) {
        CP_WAIT_1();
        __syncthreads();

        if (t + 2 < T) load_stage(t + 2, (t + 2) % NST);
        else CP_COMMIT();

        const uint32_t sA = smem_base + (uint32_t)(buf * STAGE_U) * 4;
        const uint32_t sB = sA + A_TILE_U * 4;

        // prefetch kc=0 fragments
#pragma unroll
        for (int i = 0; i < 4; i++) ldsm_x4(fa[0][i], sA + aRowB + i * 2048 + xa[0]);
#pragma unroll
        for (int jp = 0; jp < 4; jp++) ldsm_x4(fb[0][jp], sB + bRowB + jp * 2048 + xb[0]);

#pragma unroll
        for (int kc = 0; kc < 4; kc++) {
            const int pb = kc & 1;
            if (kc < 3) {
                const int nb2 = (kc + 1) & 1;
#pragma unroll
                for (int i = 0; i < 4; i++)
                    ldsm_x4(fa[nb2][i], sA + aRowB + i * 2048 + xa[kc + 1]);
#pragma unroll
                for (int jp = 0; jp < 4; jp++)
                    ldsm_x4(fb[nb2][jp], sB + bRowB + jp * 2048 + xb[kc + 1]);
            }
#pragma unroll
            for (int i = 0; i < 4; i++)
#pragma unroll
                for (int j = 0; j < 8; j++)
                    mma_f16(acc[i][j], fa[pb][i], &fb[pb][j >> 1][(j & 1) * 2]);
        }

        buf++;
        if (buf == NST) buf = 0;
    }

    // ---- epilogue -----------------------------------------------------------
#pragma unroll
    for (int i = 0; i < 4; i++) {
        int gm0 = bm + m0 + i * 16 + r;
#pragma unroll
        for (int j = 0; j < 8; j++) {
            int gn = bn + n0 + j * 8 + 2 * c;
            if (gn >= N) continue;
            float b0 = 0.f, b1 = 0.f;
            if (BIAS) {
                b0 = __half2float(__ldg(&bias[gn]));
                b1 = __half2float(__ldg(&bias[gn + 1]));
            }
            float4 v = acc[i][j];
            float x0 = v.x + b0, x1 = v.y + b1;
            float y0 = v.z + b0, y1 = v.w + b1;
            if (RELU) {
                x0 = fmaxf(x0, 0.f); x1 = fmaxf(x1, 0.f);
                y0 = fmaxf(y0, 0.f); y1 = fmaxf(y1, 0.f);
            }
            if (gm0 < M) {
                CT* p = &C[(size_t)gm0 * ldc + gn];
                if (sizeof(CT) == 2) *(half2*)p = __floats2half2_rn(x0, x1);
                else                 *(float2*)p = make_float2(x0, x1);
            }
            if (gm0 + 8 < M) {
                CT* p = &C[(size_t)(gm0 + 8) * ldc + gn];
                if (sizeof(CT) == 2) *(half2*)p = __floats2half2_rn(y0, y1);
                else                 *(float2*)p = make_float2(y0, y1);
            }
        }
    }
}

// ============================ prep kernels ==================================

__global__ void tohalf_pad_kernel(const float* __restrict__ src, __half* __restrict__ dst,
                                  int rows, int cols, int dstride)
{
    int total = rows * dstride;
    for (int i = blockIdx.x * blockDim.x + threadIdx.x; i < total; i += gridDim.x * blockDim.x) {
        int rr = i / dstride, cc = i - rr * dstride;
        float v = 0.0f;
        if (cc < cols) v = src[(size_t)rr * cols + cc];
        dst[i] = __float2half_rn(v);
    }
}

__global__ void transpose_half_kernel(const float* __restrict__ src, __half* __restrict__ dst)
{
    __shared__ float t[32][33];
    int nb = blockIdx.x * 32;
    int kb = blockIdx.y * 32;
    int x = threadIdx.x, y = threadIdx.y;   // 32 x 8
#pragma unroll
    for (int yy = y; yy < 32; yy += 8) {
        int k = kb + yy, n = nb + x;
        float v = 0.0f;
        if (k < SIZE_M && n < SIZE_N) v = src[(size_t)k * SIZE_N + n];
        t[yy][x] = v;
    }
    __syncthreads();
#pragma unroll
    for (int yy = y; yy < 32; yy += 8) {
        int n = nb + yy, k = kb + x;
        if (n < SIZE_N && k < K_PAD) dst[(size_t)n * K_PAD + k] = __float2half_rn(t[x][yy]);
    }
}

// ============================ host side =====================================

static inline dim3 grid_for(int M, int N) {
    return dim3((N + 127) / 128, (M + 127) / 128);
}

extern "C" void kernel_launch(void* const* d_in, const int* in_sizes, int n_in,
                              void* d_out, int out_size)
{
    const float* x  = (const float*)d_in[0];   // [4096, 2048]
    const float* V1 = (const float*)d_in[1];   // [5794, 2897]
    const float* V2 = (const float*)d_in[2];   // [2897, 5794]
    float* out = (float*)d_out;                // [4096, 2048]

    __half *V1h, *V2T, *xh, *Vf, *h1, *h2;
    cudaGetSymbolAddress((void**)&V1h, g_V1h);
    cudaGetSymbolAddress((void**)&V2T, g_V2T);
    cudaGetSymbolAddress((void**)&xh,  g_xh);
    cudaGetSymbolAddress((void**)&Vf,  g_Vf);
    cudaGetSymbolAddress((void**)&h1,  g_h1);
    cudaGetSymbolAddress((void**)&h2,  g_h2);

    tohalf_pad_kernel<<<2048, 256>>>(V1, V1h, SIZE_N, SIZE_M, K_PAD);
    tohalf_pad_kernel<<<2048, 256>>>(x, xh, BATCH, D_IN, D_IN);
    transpose_half_kernel<<<dim3((SIZE_N + 31) / 32, (K_PAD + 31) / 32), dim3(32, 8)>>>(V2, V2T);

    cudaFuncSetAttribute(gemm_mma<false, false, __half>,
                         cudaFuncAttributeMaxDynamicSharedMemorySize, SMEM_BYTES);
    cudaFuncSetAttribute(gemm_mma<true, true, __half>,
                         cudaFuncAttributeMaxDynamicSharedMemorySize, SMEM_BYTES);
    cudaFuncSetAttribute(gemm_mma<true, false, float>,
                         cudaFuncAttributeMaxDynamicSharedMemorySize, SMEM_BYTES);

    // 1) Vf = V1h @ V2T^T
    gemm_mma<false, false, __half><<<grid_for(SIZE_N, SIZE_N), 128, SMEM_BYTES>>>(
        V1h, V2T, nullptr, Vf, SIZE_N, SIZE_N, K_PAD, K_PAD, K_PAD, SIZE_N);

    // 2) h1 = relu(xh @ W1^T + b1)
    gemm_mma<true, true, __half><<<grid_for(BATCH, D_H), 128, SMEM_BYTES>>>(
        xh, Vf + OFF_W1, Vf + OFF_B1, h1, BATCH, D_H, D_IN, D_IN, D_IN, D_H);

    // 3) h2 = relu(h1 @ W2^T + b2)
    gemm_mma<true, true, __half><<<grid_for(BATCH, D_H), 128, SMEM_BYTES>>>(
        h1, Vf + OFF_W2, Vf + OFF_B2, h2, BATCH, D_H, D_H, D_H, D_H, D_H);

    // 4) out = h2 @ W3^T + b3
    gemm_mma<true, false, float><<<grid_for(BATCH, D_OUT), 128, SMEM_BYTES>>>(
        h2, Vf + OFF_W3, Vf + OFF_B3, out, BATCH, D_OUT, D_H, D_H, D_H, D_OUT);
}

// round 9
// speedup vs baseline: 2.1765x; 1.0083x over previous
#include <cuda_runtime.h>
#include <cuda_fp16.h>
#include <cstdint>

// ---------------------------------------------------------------------------
// FeatherNet via warp-level mma.sync fp16 (m16n8k16, fp32 accum):
//   Vf = V1@V2 ; h1 = relu(x W1^T + b1); h2 = relu(h1 W2^T + b2); out = h2 W3^T + b3
// All 4 GEMMs NT. R9: critical-first LSU ordering (ldsm kc0 before the
// 2-stage-ahead cp.async), availability-ordered kc0 prefetch, vectorized prep.
// Shape: 128x128 CTA, 4 warps 64x64, BK=64 halves, 3-stage ring, 2 CTA/SM.
// ---------------------------------------------------------------------------

#define SIZE_N 5794
#define SIZE_M 2897
#define K_PAD  2944        // 46 * 64
#define BATCH  4096
#define D_IN   2048
#define D_H    4096
#define D_OUT  2048

#define OFF_W1 0
#define OFF_B1 8388608
#define OFF_W2 8392704
#define OFF_B2 25169920
#define OFF_W3 25174016
#define OFF_B3 33562624

__device__ __align__(256) __half g_V1h[(size_t)SIZE_N * K_PAD];
__device__ __align__(256) __half g_V2T[(size_t)SIZE_N * K_PAD];
__device__ __align__(256) __half g_xh [(size_t)BATCH * D_IN];
__device__ __align__(256) __half g_Vf [(size_t)SIZE_N * SIZE_N];
__device__ __align__(256) __half g_h1 [(size_t)BATCH * D_H];
__device__ __align__(256) __half g_h2 [(size_t)BATCH * D_H];

// ============================ helpers =======================================

__device__ __forceinline__ uint32_t smem_u32(const void* p) {
    uint32_t a;
    asm("{ .reg .u64 t; cvta.to.shared.u64 t, %1; cvt.u32.u64 %0, t; }"
        : "=r"(a) : "l"(p));
    return a;
}

__device__ __forceinline__ void cp_async16(uint32_t dst, const void* src, bool valid) {
    int sz = valid ? 16 : 0;
    asm volatile("cp.async.cg.shared.global [%0], [%1], 16, %2;"
                 :: "r"(dst), "l"(src), "r"(sz) : "memory");
}
#define CP_COMMIT()  asm volatile("cp.async.commit_group;" ::: "memory")
#define CP_WAIT_1()  asm volatile("cp.async.wait_group 1;" ::: "memory")

__device__ __forceinline__ void mma_f16(float4& d, const uint32_t* a, const uint32_t* b) {
    asm volatile(
        "mma.sync.aligned.m16n8k16.row.col.f32.f16.f16.f32 "
        "{%0,%1,%2,%3}, {%4,%5,%6,%7}, {%8,%9}, {%0,%1,%2,%3};"
        : "+f"(d.x), "+f"(d.y), "+f"(d.z), "+f"(d.w)
        : "r"(a[0]), "r"(a[1]), "r"(a[2]), "r"(a[3]), "r"(b[0]), "r"(b[1]));
}

__device__ __forceinline__ void ldsm_x4(uint32_t* r, uint32_t addr) {
    asm volatile("ldmatrix.sync.aligned.m8n8.x4.shared.b16 {%0,%1,%2,%3}, [%4];"
                 : "=r"(r[0]), "=r"(r[1]), "=r"(r[2]), "=r"(r[3]) : "r"(addr));
}

// smem: tile rows of 32 u32 (=64 halves = 128B), 16B groups XOR-swizzled by row.
__device__ __forceinline__ int sw(int row, int k) {
    return row * 32 + ((((k >> 2) ^ row) & 7) << 2) + (k & 3);
}

// ============================ GEMM kernel ===================================

#define A_TILE_U 4096          // 128 rows * 32 u32
#define STAGE_U  8192          // A + B (32KB)
#define NST      3
#define SMEM_BYTES (NST * STAGE_U * 4)   // 98304

template<bool BIAS, bool RELU, typename CT>
__global__ __launch_bounds__(128, 2)
void gemm_mma(const __half* __restrict__ A, const __half* __restrict__ B,
              const __half* __restrict__ bias, CT* __restrict__ C,
              int M, int N, int K, int lda, int ldb, int ldc)
{
    extern __shared__ uint32_t smu[];
    const uint32_t smem_base = smem_u32(smu);

    const int tid = threadIdx.x;
    const int wid = tid >> 5;
    const int lid = tid & 31;
    const int r   = lid >> 2;
    const int c   = lid & 3;
    const int bm  = blockIdx.y * 128;
    const int bn  = blockIdx.x * 128;
    const int m0  = (wid & 1) * 64;
    const int n0  = (wid >> 1) * 64;

    // ldmatrix per-lane constants (row&7 == lid&7 since all offsets %8 == 0)
    const int e    = lid & 7;
    const uint32_t aRowB = (uint32_t)(m0 + ((lid >> 3) & 1) * 8 + e) * 128;
    const uint32_t bRowB = (uint32_t)(n0 + (lid >> 4) * 8 + e) * 128;
    uint32_t xa[4], xb[4];
#pragma unroll
    for (int kc = 0; kc < 4; kc++) {
        xa[kc] = (uint32_t)((((2 * kc + (lid >> 4)) ^ e) & 7) * 16);
        xb[kc] = (uint32_t)((((2 * kc + ((lid >> 3) & 1)) ^ e) & 7) * 16);
    }

    float4 acc[4][8];
#pragma unroll
    for (int i = 0; i < 4; i++)
#pragma unroll
        for (int j = 0; j < 8; j++) acc[i][j] = make_float4(0.f, 0.f, 0.f, 0.f);

    const int T = K >> 6;   // K / 64

    auto load_stage = [&](int t, int buf) {
        const int kblk = t * 64;   // halves
        uint32_t sA = smem_base + (uint32_t)(buf * STAGE_U) * 4;
        uint32_t sB = sA + A_TILE_U * 4;
#pragma unroll
        for (int i = 0; i < 8; i++) {
            int q = tid + i * 128;
            int row = q >> 3, cg = q & 7;
            int gm = bm + row;
            bool v = gm < M;
            const __half* src = A + (size_t)(v ? gm : 0) * lda + kblk + cg * 8;
            cp_async16(sA + (uint32_t)(sw(row, cg * 4)) * 4, src, v);
        }
#pragma unroll
        for (int i = 0; i < 8; i++) {
            int q = tid + i * 128;
            int row = q >> 3, cg = q & 7;
            int gn = bn + row;
            bool v = gn < N;
            const __half* src = B + (size_t)(v ? gn : 0) * ldb + kblk + cg * 8;
            cp_async16(sB + (uint32_t)(sw(row, cg * 4)) * 4, src, v);
        }
        CP_COMMIT();
    };

    load_stage(0, 0);
    if (T > 1) load_stage(1, 1); else CP_COMMIT();

    // fragment double buffers
    uint32_t fa[2][4][4], fb[2][4][4];

    int buf = 0;
    for (int t = 0; t < T; t++) {
        CP_WAIT_1();
        __syncthreads();

        const uint32_t sA = smem_base + (uint32_t)(buf * STAGE_U) * 4;
        const uint32_t sB = sA + A_TILE_U * 4;

        // ---- critical-first: kc0 fragments BEFORE the 2-stage-ahead loads.
        // Availability order: fa0, fb0..3 (feeds i=0 row of MMAs), then fa1..3.
        ldsm_x4(fa[0][0], sA + aRowB + 0 * 2048 + xa[0]);
#pragma unroll
        for (int jp = 0; jp < 4; jp++) ldsm_x4(fb[0][jp], sB + bRowB + jp * 2048 + xb[0]);
#pragma unroll
        for (int i = 1; i < 4; i++)   ldsm_x4(fa[0][i], sA + aRowB + i * 2048 + xa[0]);

        if (t + 2 < T) load_stage(t + 2, (t + 2) % NST);
        else CP_COMMIT();

#pragma unroll
        for (int kc = 0; kc < 4; kc++) {
            const int pb = kc & 1;
            if (kc < 3) {
                const int nb2 = (kc + 1) & 1;
#pragma unroll
                for (int i = 0; i < 4; i++)
                    ldsm_x4(fa[nb2][i], sA + aRowB + i * 2048 + xa[kc + 1]);
#pragma unroll
                for (int jp = 0; jp < 4; jp++)
                    ldsm_x4(fb[nb2][jp], sB + bRowB + jp * 2048 + xb[kc + 1]);
            }
#pragma unroll
            for (int i = 0; i < 4; i++)
#pragma unroll
                for (int j = 0; j < 8; j++)
                    mma_f16(acc[i][j], fa[pb][i], &fb[pb][j >> 1][(j & 1) * 2]);
        }

        buf++;
        if (buf == NST) buf = 0;
    }

    // ---- epilogue -----------------------------------------------------------
#pragma unroll
    for (int i = 0; i < 4; i++) {
        int gm0 = bm + m0 + i * 16 + r;
#pragma unroll
        for (int j = 0; j < 8; j++) {
            int gn = bn + n0 + j * 8 + 2 * c;
            if (gn >= N) continue;
            float b0 = 0.f, b1 = 0.f;
            if (BIAS) {
                b0 = __half2float(__ldg(&bias[gn]));
                b1 = __half2float(__ldg(&bias[gn + 1]));
            }
            float4 v = acc[i][j];
            float x0 = v.x + b0, x1 = v.y + b1;
            float y0 = v.z + b0, y1 = v.w + b1;
            if (RELU) {
                x0 = fmaxf(x0, 0.f); x1 = fmaxf(x1, 0.f);
                y0 = fmaxf(y0, 0.f); y1 = fmaxf(y1, 0.f);
            }
            if (gm0 < M) {
                CT* p = &C[(size_t)gm0 * ldc + gn];
                if (sizeof(CT) == 2) *(half2*)p = __floats2half2_rn(x0, x1);
                else                 *(float2*)p = make_float2(x0, x1);
            }
            if (gm0 + 8 < M) {
                CT* p = &C[(size_t)(gm0 + 8) * ldc + gn];
                if (sizeof(CT) == 2) *(half2*)p = __floats2half2_rn(y0, y1);
                else                 *(float2*)p = make_float2(y0, y1);
            }
        }
    }
}

// ============================ prep kernels ==================================

// half2-vectorized: dst[rr][cc..cc+1] = half(src) or 0-pad. dstride even.
__global__ void tohalf_pad_kernel(const float* __restrict__ src, __half* __restrict__ dst,
                                  int rows, int cols, int dstride)
{
    const int pitchp = dstride >> 1;
    int totalp = rows * pitchp;
    for (int i = blockIdx.x * blockDim.x + threadIdx.x; i < totalp; i += gridDim.x * blockDim.x) {
        int rr = i / pitchp, p = i - rr * pitchp;
        int cc = p * 2;
        float v0 = (cc < cols)     ? src[(size_t)rr * cols + cc]     : 0.f;
        float v1 = (cc + 1 < cols) ? src[(size_t)rr * cols + cc + 1] : 0.f;
        *(half2*)&dst[(size_t)rr * dstride + cc] = __floats2half2_rn(v0, v1);
    }
}

// V2 [SIZE_M x SIZE_N] f32 -> V2T [SIZE_N x K_PAD] f16, zero-padded K, half2 stores
__global__ void transpose_half_kernel(const float* __restrict__ src, __half* __restrict__ dst)
{
    __shared__ float t[32][33];
    int nb = blockIdx.x * 32;
    int kb = blockIdx.y * 32;
    int x = threadIdx.x, y = threadIdx.y;   // 32 x 8
#pragma unroll
    for (int yy = y; yy < 32; yy += 8) {
        int k = kb + yy, n = nb + x;
        float v = 0.0f;
        if (k < SIZE_M && n < SIZE_N) v = src[(size_t)k * SIZE_N + n];
        t[yy][x] = v;
    }
    __syncthreads();
    if (x < 16) {
#pragma unroll
        for (int yy = y; yy < 32; yy += 8) {
            int n = nb + yy, k2 = kb + 2 * x;
            if (n < SIZE_N && k2 < K_PAD) {
                half2 h = __floats2half2_rn(t[2 * x][yy], t[2 * x + 1][yy]);
                *(half2*)&dst[(size_t)n * K_PAD + k2] = h;
            }
        }
    }
}

// ============================ host side =====================================

static inline dim3 grid_for(int M, int N) {
    return dim3((N + 127) / 128, (M + 127) / 128);
}

extern "C" void kernel_launch(void* const* d_in, const int* in_sizes, int n_in,
                              void* d_out, int out_size)
{
    const float* x  = (const float*)d_in[0];   // [4096, 2048]
    const float* V1 = (const float*)d_in[1];   // [5794, 2897]
    const float* V2 = (const float*)d_in[2];   // [2897, 5794]
    float* out = (float*)d_out;                // [4096, 2048]

    __half *V1h, *V2T, *xh, *Vf, *h1, *h2;
    cudaGetSymbolAddress((void**)&V1h, g_V1h);
    cudaGetSymbolAddress((void**)&V2T, g_V2T);
    cudaGetSymbolAddress((void**)&xh,  g_xh);
    cudaGetSymbolAddress((void**)&Vf,  g_Vf);
    cudaGetSymbolAddress((void**)&h1,  g_h1);
    cudaGetSymbolAddress((void**)&h2,  g_h2);

    tohalf_pad_kernel<<<2048, 256>>>(V1, V1h, SIZE_N, SIZE_M, K_PAD);
    tohalf_pad_kernel<<<1024, 256>>>(x, xh, BATCH, D_IN, D_IN);
    transpose_half_kernel<<<dim3((SIZE_N + 31) / 32, (K_PAD + 31) / 32), dim3(32, 8)>>>(V2, V2T);

    cudaFuncSetAttribute(gemm_mma<false, false, __half>,
                         cudaFuncAttributeMaxDynamicSharedMemorySize, SMEM_BYTES);
    cudaFuncSetAttribute(gemm_mma<true, true, __half>,
                         cudaFuncAttributeMaxDynamicSharedMemorySize, SMEM_BYTES);
    cudaFuncSetAttribute(gemm_mma<true, false, float>,
                         cudaFuncAttributeMaxDynamicSharedMemorySize, SMEM_BYTES);

    // 1) Vf = V1h @ V2T^T
    gemm_mma<false, false, __half><<<grid_for(SIZE_N, SIZE_N), 128, SMEM_BYTES>>>(
        V1h, V2T, nullptr, Vf, SIZE_N, SIZE_N, K_PAD, K_PAD, K_PAD, SIZE_N);

    // 2) h1 = relu(xh @ W1^T + b1)
    gemm_mma<true, true, __half><<<grid_for(BATCH, D_H), 128, SMEM_BYTES>>>(
        xh, Vf + OFF_W1, Vf + OFF_B1, h1, BATCH, D_H, D_IN, D_IN, D_IN, D_H);

    // 3) h2 = relu(h1 @ W2^T + b2)
    gemm_mma<true, true, __half><<<grid_for(BATCH, D_H), 128, SMEM_BYTES>>>(
        h1, Vf + OFF_W2, Vf + OFF_B2, h2, BATCH, D_H, D_H, D_H, D_H, D_H);

    // 4) out = h2 @ W3^T + b3
    gemm_mma<true, false, float><<<grid_for(BATCH, D_OUT), 128, SMEM_BYTES>>>(
        h2, Vf + OFF_W3, Vf + OFF_B3, out, BATCH, D_OUT, D_H, D_H, D_H, D_OUT);
}

// round 10
// speedup vs baseline: 2.4458x; 1.1237x over previous
#include <cuda_runtime.h>
#include <cuda.h>
#include <cuda_fp16.h>
#include <cstdint>

// ---------------------------------------------------------------------------
// FeatherNet via mma.sync fp16 + TMA (cp.async.bulk.tensor, sm_90 baseline):
//   Vf = V1@V2 ; h1 = relu(x W1^T + b1); h2 = relu(h1 W2^T + b2); out = h2 W3^T + b3
// All 4 GEMMs NT. R10: the cp.async loader (4096 LDGSTS/SM/stage — LSU
// saturation, the measured tensor-pipe bubble) is replaced by 2 TMA loads
// per stage + mbarrier full/empty rings. TMA SWIZZLE_128B == our sw() layout,
// so ldmatrix/MMA fragments are unchanged. No per-stage __syncthreads.
// Shape: 128x128 CTA, 4 warps 64x64, BK=64 halves, 3-stage ring, 2 CTA/SM.
// ---------------------------------------------------------------------------

#define SIZE_N 5794
#define SIZE_M 2897
#define K_PAD  2944        // 46 * 64
#define BATCH  4096
#define D_IN   2048
#define D_H    4096
#define D_OUT  2048

#define OFF_W1 0
#define OFF_B1 8388608
#define OFF_W2 8392704
#define OFF_B2 25169920
#define OFF_W3 25174016
#define OFF_B3 33562624

__device__ __align__(256) __half g_V1h[(size_t)SIZE_N * K_PAD];
__device__ __align__(256) __half g_V2T[(size_t)SIZE_N * K_PAD];
__device__ __align__(256) __half g_xh [(size_t)BATCH * D_IN];
__device__ __align__(256) __half g_Vf [(size_t)SIZE_N * SIZE_N];
__device__ __align__(256) __half g_h1 [(size_t)BATCH * D_H];
__device__ __align__(256) __half g_h2 [(size_t)BATCH * D_H];

// ============================ PTX helpers ===================================

__device__ __forceinline__ uint32_t smem_u32(const void* p) {
    uint32_t a;
    asm("{ .reg .u64 t; cvta.to.shared.u64 t, %1; cvt.u32.u64 %0, t; }"
        : "=r"(a) : "l"(p));
    return a;
}

#define MBARRIER_INIT(addr, cnt) \
    asm volatile("mbarrier.init.shared.b64 [%0], %1;" \
                 :: "r"((uint32_t)(addr)), "r"((uint32_t)(cnt)) : "memory")

#define MBARRIER_EXPECT_TX(addr, bytes) \
    asm volatile("mbarrier.arrive.expect_tx.shared.b64 _, [%0], %1;" \
                 :: "r"((uint32_t)(addr)), "r"((uint32_t)(bytes)) : "memory")

#define MBARRIER_ARRIVE(addr) \
    asm volatile("mbarrier.arrive.shared.b64 _, [%0];" \
                 :: "r"((uint32_t)(addr)) : "memory")

#define MBARRIER_WAIT_PARITY(addr, par) do {                                         \
    uint32_t _m = (uint32_t)(addr); uint32_t _p = (uint32_t)(par); uint32_t _d;      \
    asm volatile("{\n\t.reg .pred p;\n\t"                                            \
        "mbarrier.try_wait.parity.acquire.cta.shared::cta.b64 p, [%1], %2;\n\t"      \
        "selp.b32 %0, 1, 0, p;\n\t}"                                                 \
        : "=r"(_d) : "r"(_m), "r"(_p) : "memory");                                   \
    if (!_d) {                                                                       \
        asm volatile("{\n\t.reg .pred P1;\n\t"                                       \
            "WL_%=:\n\t"                                                             \
            "mbarrier.try_wait.parity.acquire.cta.shared::cta.b64 P1, [%0], %1, 0x989680;\n\t" \
            "@P1 bra.uni WD_%=;\n\t"                                                 \
            "bra.uni WL_%=;\n\t"                                                     \
            "WD_%=:\n\t}"                                                            \
            :: "r"(_m), "r"(_p) : "memory");                                         \
    }                                                                                \
} while (0)

__device__ __forceinline__ void tma2d(uint32_t dst, const CUtensorMap* m,
                                      int cx, int cy, uint32_t bar) {
    asm volatile(
        "cp.async.bulk.tensor.2d.shared::cta.global.tile.mbarrier::complete_tx::bytes "
        "[%0], [%1, {%2, %3}], [%4];"
        :: "r"(dst), "l"(m), "r"(cx), "r"(cy), "r"(bar) : "memory");
}

__device__ __forceinline__ void mma_f16(float4& d, const uint32_t* a, const uint32_t* b) {
    asm volatile(
        "mma.sync.aligned.m16n8k16.row.col.f32.f16.f16.f32 "
        "{%0,%1,%2,%3}, {%4,%5,%6,%7}, {%8,%9}, {%0,%1,%2,%3};"
        : "+f"(d.x), "+f"(d.y), "+f"(d.z), "+f"(d.w)
        : "r"(a[0]), "r"(a[1]), "r"(a[2]), "r"(a[3]), "r"(b[0]), "r"(b[1]));
}

__device__ __forceinline__ void ldsm_x4(uint32_t* r, uint32_t addr) {
    asm volatile("ldmatrix.sync.aligned.m8n8.x4.shared.b16 {%0,%1,%2,%3}, [%4];"
                 : "=r"(r[0]), "=r"(r[1]), "=r"(r[2]), "=r"(r[3]) : "r"(addr));
}

// ============================ GEMM kernel ===================================
// Stage = A tile 16KB + B tile 16KB (128 rows x 128B, TMA SW128 layout).

#define NST 3
#define STAGE_BYTES 32768
#define SMEM_REQ 99392     // 48B barriers + <=1024B align slack + 3*32768

template<bool BIAS, bool RELU, typename CT>
__global__ __launch_bounds__(128, 2)
void gemm_tma(const __grid_constant__ CUtensorMap tmA,
              const __grid_constant__ CUtensorMap tmB,
              const __half* __restrict__ bias, CT* __restrict__ C,
              int M, int N, int T, int ldc)
{
    extern __shared__ uint32_t smu[];
    const uint32_t sbr = smem_u32(smu);
    const uint32_t st0 = (sbr + 48 + 1023) & ~1023u;   // 1024B-aligned stages

    const int tid = threadIdx.x;
    const int wid = tid >> 5;
    const int lid = tid & 31;
    const int r   = lid >> 2;
    const int c   = lid & 3;
    const int bm  = blockIdx.y * 128;
    const int bn  = blockIdx.x * 128;
    const int m0  = (wid & 1) * 64;
    const int n0  = (wid >> 1) * 64;

    if (tid == 0) {
#pragma unroll
        for (int s = 0; s < NST; s++) {
            MBARRIER_INIT(sbr + 16 * s, 1);        // full[s]: tx-based
            MBARRIER_INIT(sbr + 16 * s + 8, 128);  // empty[s]: all threads
        }
    }
    __syncthreads();

    // ldmatrix per-lane constants (row&7 == lid&7; all row offsets %8 == 0)
    const int e    = lid & 7;
    const uint32_t aRowB = (uint32_t)(m0 + ((lid >> 3) & 1) * 8 + e) * 128;
    const uint32_t bRowB = (uint32_t)(n0 + (lid >> 4) * 8 + e) * 128;
    uint32_t xa[4], xb[4];
#pragma unroll
    for (int kc = 0; kc < 4; kc++) {
        xa[kc] = (uint32_t)((((2 * kc + (lid >> 4)) ^ e) & 7) * 16);
        xb[kc] = (uint32_t)((((2 * kc + ((lid >> 3) & 1)) ^ e) & 7) * 16);
    }

    float4 acc[4][8];
#pragma unroll
    for (int i = 0; i < 4; i++)
#pragma unroll
        for (int j = 0; j < 8; j++) acc[i][j] = make_float4(0.f, 0.f, 0.f, 0.f);

    // ---- prologue: issue stages 0 and 1 (buffers free by construction) ----
    if (tid == 0) {
        int npro = T < 2 ? T : 2;
        for (int p = 0; p < npro; p++) {
            MBARRIER_EXPECT_TX(sbr + 16 * p, STAGE_BYTES);
            tma2d(st0 + p * STAGE_BYTES,         &tmA, p * 64, bm, sbr + 16 * p);
            tma2d(st0 + p * STAGE_BYTES + 16384, &tmB, p * 64, bn, sbr + 16 * p);
        }
    }

    uint32_t fa[2][4][4], fb[2][4][4];

    int s = 0, fph = 0;        // consumer: full[s], parity fph
    int s2 = 2, eph = 1;       // producer: next issue slot (t+2), empty parity
    for (int t = 0; t < T; t++) {
        MBARRIER_WAIT_PARITY(sbr + 16 * s, fph);   // acquire: stage t resident

        const uint32_t sA = st0 + (uint32_t)s * STAGE_BYTES;
        const uint32_t sB = sA + 16384;

        // kc0 fragments, availability order (fa0, fb0..3, fa1..3)
        ldsm_x4(fa[0][0], sA + aRowB + 0 * 2048 + xa[0]);
#pragma unroll
        for (int jp = 0; jp < 4; jp++) ldsm_x4(fb[0][jp], sB + bRowB + jp * 2048 + xb[0]);
#pragma unroll
        for (int i = 1; i < 4; i++)   ldsm_x4(fa[0][i], sA + aRowB + i * 2048 + xa[0]);

        // producer: issue stage t+2 into slot s2
        if (tid == 0 && t + 2 < T) {
            MBARRIER_WAIT_PARITY(sbr + 16 * s2 + 8, eph);   // backpressure
            MBARRIER_EXPECT_TX(sbr + 16 * s2, STAGE_BYTES);
            uint32_t dA = st0 + (uint32_t)s2 * STAGE_BYTES;
            tma2d(dA,         &tmA, (t + 2) * 64, bm, sbr + 16 * s2);
            tma2d(dA + 16384, &tmB, (t + 2) * 64, bn, sbr + 16 * s2);
        }

#pragma unroll
        for (int kc = 0; kc < 4; kc++) {
            const int pb = kc & 1;
            if (kc < 3) {
                const int nb2 = (kc + 1) & 1;
#pragma unroll
                for (int i = 0; i < 4; i++)
                    ldsm_x4(fa[nb2][i], sA + aRowB + i * 2048 + xa[kc + 1]);
#pragma unroll
                for (int jp = 0; jp < 4; jp++)
                    ldsm_x4(fb[nb2][jp], sB + bRowB + jp * 2048 + xb[kc + 1]);
            }
#pragma unroll
            for (int i = 0; i < 4; i++)
#pragma unroll
                for (int j = 0; j < 8; j++)
                    mma_f16(acc[i][j], fa[pb][i], &fb[pb][j >> 1][(j & 1) * 2]);
        }

        MBARRIER_ARRIVE(sbr + 16 * s + 8);   // release stage t's buffer

        if (++s == NST)  { s = 0;  fph ^= 1; }
        if (++s2 == NST) { s2 = 0; eph ^= 1; }
    }

    // ---- epilogue -----------------------------------------------------------
#pragma unroll
    for (int i = 0; i < 4; i++) {
        int gm0 = bm + m0 + i * 16 + r;
#pragma unroll
        for (int j = 0; j < 8; j++) {
            int gn = bn + n0 + j * 8 + 2 * c;
            if (gn >= N) continue;
            float b0 = 0.f, b1 = 0.f;
            if (BIAS) {
                b0 = __half2float(__ldg(&bias[gn]));
                b1 = __half2float(__ldg(&bias[gn + 1]));
            }
            float4 v = acc[i][j];
            float x0 = v.x + b0, x1 = v.y + b1;
            float y0 = v.z + b0, y1 = v.w + b1;
            if (RELU) {
                x0 = fmaxf(x0, 0.f); x1 = fmaxf(x1, 0.f);
                y0 = fmaxf(y0, 0.f); y1 = fmaxf(y1, 0.f);
            }
            if (gm0 < M) {
                CT* p = &C[(size_t)gm0 * ldc + gn];
                if (sizeof(CT) == 2) *(half2*)p = __floats2half2_rn(x0, x1);
                else                 *(float2*)p = make_float2(x0, x1);
            }
            if (gm0 + 8 < M) {
                CT* p = &C[(size_t)(gm0 + 8) * ldc + gn];
                if (sizeof(CT) == 2) *(half2*)p = __floats2half2_rn(y0, y1);
                else                 *(float2*)p = make_float2(y0, y1);
            }
        }
    }
}

// ============================ prep kernels ==================================

__global__ void tohalf_pad_kernel(const float* __restrict__ src, __half* __restrict__ dst,
                                  int rows, int cols, int dstride)
{
    const int pitchp = dstride >> 1;
    int totalp = rows * pitchp;
    for (int i = blockIdx.x * blockDim.x + threadIdx.x; i < totalp; i += gridDim.x * blockDim.x) {
        int rr = i / pitchp, p = i - rr * pitchp;
        int cc = p * 2;
        float v0 = (cc < cols)     ? src[(size_t)rr * cols + cc]     : 0.f;
        float v1 = (cc + 1 < cols) ? src[(size_t)rr * cols + cc + 1] : 0.f;
        *(half2*)&dst[(size_t)rr * dstride + cc] = __floats2half2_rn(v0, v1);
    }
}

__global__ void transpose_half_kernel(const float* __restrict__ src, __half* __restrict__ dst)
{
    __shared__ float t[32][33];
    int nb = blockIdx.x * 32;
    int kb = blockIdx.y * 32;
    int x = threadIdx.x, y = threadIdx.y;   // 32 x 8
#pragma unroll
    for (int yy = y; yy < 32; yy += 8) {
        int k = kb + yy, n = nb + x;
        float v = 0.0f;
        if (k < SIZE_M && n < SIZE_N) v = src[(size_t)k * SIZE_N + n];
        t[yy][x] = v;
    }
    __syncthreads();
    if (x < 16) {
#pragma unroll
        for (int yy = y; yy < 32; yy += 8) {
            int n = nb + yy, k2 = kb + 2 * x;
            if (n < SIZE_N && k2 < K_PAD) {
                half2 h = __floats2half2_rn(t[2 * x][yy], t[2 * x + 1][yy]);
                *(half2*)&dst[(size_t)n * K_PAD + k2] = h;
            }
        }
    }
}

// ============================ host side =====================================

typedef CUresult (*tmap_encode_fn)(
    CUtensorMap*, CUtensorMapDataType, cuuint32_t, void*,
    const cuuint64_t*, const cuuint64_t*, const cuuint32_t*, const cuuint32_t*,
    CUtensorMapInterleave, CUtensorMapSwizzle, CUtensorMapL2promotion, CUtensorMapFloatOOBfill);

static void make_map(CUtensorMap* m, void* ptr, uint64_t k_elems, uint64_t rows,
                     uint64_t stride_bytes)
{
    static tmap_encode_fn enc = nullptr;
    if (!enc) {
        cudaDriverEntryPointQueryResult qr;
        cudaGetDriverEntryPointByVersion("cuTensorMapEncodeTiled", (void**)&enc,
                                         12000, cudaEnableDefault, &qr);
    }
    cuuint64_t dims[2]    = {k_elems, rows};
    cuuint64_t strides[1] = {stride_bytes};
    cuuint32_t box[2]     = {64, 128};      // 64 halves = 128B inner (SW128 span)
    cuuint32_t es[2]      = {1, 1};
    enc(m, CU_TENSOR_MAP_DATA_TYPE_FLOAT16, 2, ptr, dims, strides, box, es,
        CU_TENSOR_MAP_INTERLEAVE_NONE, CU_TENSOR_MAP_SWIZZLE_128B,
        CU_TENSOR_MAP_L2_PROMOTION_L2_128B, CU_TENSOR_MAP_FLOAT_OOB_FILL_NONE);
}

static inline dim3 grid_for(int M, int N) {
    return dim3((N + 127) / 128, (M + 127) / 128);
}

extern "C" void kernel_launch(void* const* d_in, const int* in_sizes, int n_in,
                              void* d_out, int out_size)
{
    const float* x  = (const float*)d_in[0];   // [4096, 2048]
    const float* V1 = (const float*)d_in[1];   // [5794, 2897]
    const float* V2 = (const float*)d_in[2];   // [2897, 5794]
    float* out = (float*)d_out;                // [4096, 2048]

    __half *V1h, *V2T, *xh, *Vf, *h1, *h2;
    cudaGetSymbolAddress((void**)&V1h, g_V1h);
    cudaGetSymbolAddress((void**)&V2T, g_V2T);
    cudaGetSymbolAddress((void**)&xh,  g_xh);
    cudaGetSymbolAddress((void**)&Vf,  g_Vf);
    cudaGetSymbolAddress((void**)&h1,  g_h1);
    cudaGetSymbolAddress((void**)&h2,  g_h2);

    tohalf_pad_kernel<<<2048, 256>>>(V1, V1h, SIZE_N, SIZE_M, K_PAD);
    tohalf_pad_kernel<<<1024, 256>>>(x, xh, BATCH, D_IN, D_IN);
    transpose_half_kernel<<<dim3((SIZE_N + 31) / 32, (K_PAD + 31) / 32), dim3(32, 8)>>>(V2, V2T);

    // tensor maps: {K elements, rows, row stride}
    CUtensorMap mA0, mB0, mA1, mB1, mA2, mB2, mA3, mB3;
    make_map(&mA0, V1h,          K_PAD, SIZE_N, (uint64_t)K_PAD * 2);
    make_map(&mB0, V2T,          K_PAD, SIZE_N, (uint64_t)K_PAD * 2);
    make_map(&mA1, xh,           D_IN,  BATCH,  (uint64_t)D_IN * 2);
    make_map(&mB1, Vf + OFF_W1,  D_IN,  D_H,    (uint64_t)D_IN * 2);
    make_map(&mA2, h1,           D_H,   BATCH,  (uint64_t)D_H * 2);
    make_map(&mB2, Vf + OFF_W2,  D_H,   D_H,    (uint64_t)D_H * 2);
    make_map(&mA3, h2,           D_H,   BATCH,  (uint64_t)D_H * 2);
    make_map(&mB3, Vf + OFF_W3,  D_H,   D_OUT,  (uint64_t)D_H * 2);

    cudaFuncSetAttribute(gemm_tma<false, false, __half>,
                         cudaFuncAttributeMaxDynamicSharedMemorySize, SMEM_REQ);
    cudaFuncSetAttribute(gemm_tma<true, true, __half>,
                         cudaFuncAttributeMaxDynamicSharedMemorySize, SMEM_REQ);
    cudaFuncSetAttribute(gemm_tma<true, false, float>,
                         cudaFuncAttributeMaxDynamicSharedMemorySize, SMEM_REQ);

    // 1) Vf = V1h @ V2T^T
    gemm_tma<false, false, __half><<<grid_for(SIZE_N, SIZE_N), 128, SMEM_REQ>>>(
        mA0, mB0, nullptr, Vf, SIZE_N, SIZE_N, K_PAD / 64, SIZE_N);

    // 2) h1 = relu(xh @ W1^T + b1)
    gemm_tma<true, true, __half><<<grid_for(BATCH, D_H), 128, SMEM_REQ>>>(
        mA1, mB1, Vf + OFF_B1, h1, BATCH, D_H, D_IN / 64, D_H);

    // 3) h2 = relu(h1 @ W2^T + b2)
    gemm_tma<true, true, __half><<<grid_for(BATCH, D_H), 128, SMEM_REQ>>>(
        mA2, mB2, Vf + OFF_B2, h2, BATCH, D_H, D_H / 64, D_H);

    // 4) out = h2 @ W3^T + b3
    gemm_tma<true, false, float><<<grid_for(BATCH, D_OUT), 128, SMEM_REQ>>>(
        mA3, mB3, Vf + OFF_B3, out, BATCH, D_OUT, D_H / 64, D_OUT);
}

// round 11
// speedup vs baseline: 2.5162x; 1.0288x over previous
#include <cuda_runtime.h>
#include <cuda.h>
#include <cuda_fp16.h>
#include <cstdint>

// ---------------------------------------------------------------------------
// FeatherNet, single mega-launch: all 4 GEMMs in one grid with device-side
// release/acquire dependency counters, so later GEMMs backfill the wave tails
// of earlier ones (4 separate launches = 18 wave-times; merged ~15.3).
//   seg0: Vf = V1@V2                    (2116 CTAs, ids 0..2115)
//   seg1: h1 = relu(x W1^T + b1)        (1024 CTAs)   waits rows<1536 of Vf
//   seg2: h2 = relu(h1 W2^T + b2)       (1024 CTAs)   waits rows<4352 + all h1
//   seg3: out = h2 W3^T + b3            ( 512 CTAs)   waits all Vf + all h2
// GEMM body identical to R10 (TMA + mbarrier ring + ldmatrix + mma.sync fp16).
// ---------------------------------------------------------------------------

#define SIZE_N 5794
#define SIZE_M 2897
#define K_PAD  2944        // 46 * 64
#define BATCH  4096
#define D_IN   2048
#define D_H    4096
#define D_OUT  2048

#define OFF_W1 0
#define OFF_B1 8388608
#define OFF_W2 8392704
#define OFF_B2 25169920
#define OFF_W3 25174016
#define OFF_B3 33562624

#define G0_CTAS 2116       // 46 x 46
#define L1_CTAS 1024       // 32 x 32
#define L2_CTAS 1024
#define L3_CTAS 512        // 32 y x 16 x
#define TGT_A   552        // 12 row-tiles x 46
#define TGT_B   1564       // 34 row-tiles x 46

__device__ __align__(256) __half g_V1h[(size_t)SIZE_N * K_PAD];
__device__ __align__(256) __half g_V2T[(size_t)SIZE_N * K_PAD];
__device__ __align__(256) __half g_xh [(size_t)BATCH * D_IN];
__device__ __align__(256) __half g_Vf [(size_t)SIZE_N * SIZE_N];
__device__ __align__(256) __half g_h1 [(size_t)BATCH * D_H];
__device__ __align__(256) __half g_h2 [(size_t)BATCH * D_H];

__device__ uint32_t g_cA, g_cB, g_cC, g_c1, g_c2;

// ============================ PTX helpers ===================================

__device__ __forceinline__ uint32_t smem_u32(const void* p) {
    uint32_t a;
    asm("{ .reg .u64 t; cvta.to.shared.u64 t, %1; cvt.u32.u64 %0, t; }"
        : "=r"(a) : "l"(p));
    return a;
}

#define MBARRIER_INIT(addr, cnt) \
    asm volatile("mbarrier.init.shared.b64 [%0], %1;" \
                 :: "r"((uint32_t)(addr)), "r"((uint32_t)(cnt)) : "memory")

#define MBARRIER_EXPECT_TX(addr, bytes) \
    asm volatile("mbarrier.arrive.expect_tx.shared.b64 _, [%0], %1;" \
                 :: "r"((uint32_t)(addr)), "r"((uint32_t)(bytes)) : "memory")

#define MBARRIER_ARRIVE(addr) \
    asm volatile("mbarrier.arrive.shared.b64 _, [%0];" \
                 :: "r"((uint32_t)(addr)) : "memory")

#define MBARRIER_WAIT_PARITY(addr, par) do {                                         \
    uint32_t _m = (uint32_t)(addr); uint32_t _p = (uint32_t)(par); uint32_t _d;      \
    asm volatile("{\n\t.reg .pred p;\n\t"                                            \
        "mbarrier.try_wait.parity.acquire.cta.shared::cta.b64 p, [%1], %2;\n\t"      \
        "selp.b32 %0, 1, 0, p;\n\t}"                                                 \
        : "=r"(_d) : "r"(_m), "r"(_p) : "memory");                                   \
    if (!_d) {                                                                       \
        asm volatile("{\n\t.reg .pred P1;\n\t"                                       \
            "WL_%=:\n\t"                                                             \
            "mbarrier.try_wait.parity.acquire.cta.shared::cta.b64 P1, [%0], %1, 0x989680;\n\t" \
            "@P1 bra.uni WD_%=;\n\t"                                                 \
            "bra.uni WL_%=;\n\t"                                                     \
            "WD_%=:\n\t}"                                                            \
            :: "r"(_m), "r"(_p) : "memory");                                         \
    }                                                                                \
} while (0)

__device__ __forceinline__ void tma2d(uint32_t dst, const CUtensorMap* m,
                                      int cx, int cy, uint32_t bar) {
    asm volatile(
        "cp.async.bulk.tensor.2d.shared::cta.global.tile.mbarrier::complete_tx::bytes "
        "[%0], [%1, {%2, %3}], [%4];"
        :: "r"(dst), "l"(m), "r"(cx), "r"(cy), "r"(bar) : "memory");
}

__device__ __forceinline__ void mma_f16(float4& d, const uint32_t* a, const uint32_t* b) {
    asm volatile(
        "mma.sync.aligned.m16n8k16.row.col.f32.f16.f16.f32 "
        "{%0,%1,%2,%3}, {%4,%5,%6,%7}, {%8,%9}, {%0,%1,%2,%3};"
        : "+f"(d.x), "+f"(d.y), "+f"(d.z), "+f"(d.w)
        : "r"(a[0]), "r"(a[1]), "r"(a[2]), "r"(a[3]), "r"(b[0]), "r"(b[1]));
}

__device__ __forceinline__ void ldsm_x4(uint32_t* r, uint32_t addr) {
    asm volatile("ldmatrix.sync.aligned.m8n8.x4.shared.b16 {%0,%1,%2,%3}, [%4];"
                 : "=r"(r[0]), "=r"(r[1]), "=r"(r[2]), "=r"(r[3]) : "r"(addr));
}

// cross-CTA dependency primitives
__device__ __forceinline__ uint32_t ld_acq(const uint32_t* p) {
    uint32_t v;
    asm volatile("ld.acquire.gpu.u32 %0, [%1];" : "=r"(v) : "l"(p) : "memory");
    return v;
}
__device__ __forceinline__ void red_rel(uint32_t* p) {
    asm volatile("red.release.gpu.add.u32 [%0], 1;" :: "l"(p) : "memory");
}
__device__ __forceinline__ void spinc(const uint32_t* p, uint32_t tgt) {
    while (ld_acq(p) < tgt) __nanosleep(128);
}
#define FENCE_PROXY_ASYNC() asm volatile("fence.proxy.async;" ::: "memory")

// ============================ GEMM body =====================================
// Stage = A tile 16KB + B tile 16KB (128 rows x 128B, TMA SW128 layout).

#define NST 3
#define STAGE_BYTES 32768
#define SMEM_REQ 99392

template<bool BIAS, bool RELU, typename CT>
__device__ __forceinline__ void gemm_body(
    uint32_t* smu,
    const CUtensorMap* tmA, const CUtensorMap* tmB,
    const __half* __restrict__ bias, CT* __restrict__ C,
    int M, int N, int T, int ldc, int bx, int by)
{
    const uint32_t sbr = smem_u32(smu);
    const uint32_t st0 = (sbr + 48 + 1023) & ~1023u;

    const int tid = threadIdx.x;
    const int wid = tid >> 5;
    const int lid = tid & 31;
    const int r   = lid >> 2;
    const int c   = lid & 3;
    const int bm  = by * 128;
    const int bn  = bx * 128;
    const int m0  = (wid & 1) * 64;
    const int n0  = (wid >> 1) * 64;

    if (tid == 0) {
#pragma unroll
        for (int s = 0; s < NST; s++) {
            MBARRIER_INIT(sbr + 16 * s, 1);
            MBARRIER_INIT(sbr + 16 * s + 8, 128);
        }
    }
    __syncthreads();

    const int e    = lid & 7;
    const uint32_t aRowB = (uint32_t)(m0 + ((lid >> 3) & 1) * 8 + e) * 128;
    const uint32_t bRowB = (uint32_t)(n0 + (lid >> 4) * 8 + e) * 128;
    uint32_t xa[4], xb[4];
#pragma unroll
    for (int kc = 0; kc < 4; kc++) {
        xa[kc] = (uint32_t)((((2 * kc + (lid >> 4)) ^ e) & 7) * 16);
        xb[kc] = (uint32_t)((((2 * kc + ((lid >> 3) & 1)) ^ e) & 7) * 16);
    }

    float4 acc[4][8];
#pragma unroll
    for (int i = 0; i < 4; i++)
#pragma unroll
        for (int j = 0; j < 8; j++) acc[i][j] = make_float4(0.f, 0.f, 0.f, 0.f);

    if (tid == 0) {
        int npro = T < 2 ? T : 2;
        for (int p = 0; p < npro; p++) {
            MBARRIER_EXPECT_TX(sbr + 16 * p, STAGE_BYTES);
            tma2d(st0 + p * STAGE_BYTES,         tmA, p * 64, bm, sbr + 16 * p);
            tma2d(st0 + p * STAGE_BYTES + 16384, tmB, p * 64, bn, sbr + 16 * p);
        }
    }

    uint32_t fa[2][4][4], fb[2][4][4];

    int s = 0, fph = 0;
    int s2 = 2, eph = 1;
    for (int t = 0; t < T; t++) {
        MBARRIER_WAIT_PARITY(sbr + 16 * s, fph);

        const uint32_t sA = st0 + (uint32_t)s * STAGE_BYTES;
        const uint32_t sB = sA + 16384;

        ldsm_x4(fa[0][0], sA + aRowB + 0 * 2048 + xa[0]);
#pragma unroll
        for (int jp = 0; jp < 4; jp++) ldsm_x4(fb[0][jp], sB + bRowB + jp * 2048 + xb[0]);
#pragma unroll
        for (int i = 1; i < 4; i++)   ldsm_x4(fa[0][i], sA + aRowB + i * 2048 + xa[0]);

        if (tid == 0 && t + 2 < T) {
            MBARRIER_WAIT_PARITY(sbr + 16 * s2 + 8, eph);
            MBARRIER_EXPECT_TX(sbr + 16 * s2, STAGE_BYTES);
            uint32_t dA = st0 + (uint32_t)s2 * STAGE_BYTES;
            tma2d(dA,         tmA, (t + 2) * 64, bm, sbr + 16 * s2);
            tma2d(dA + 16384, tmB, (t + 2) * 64, bn, sbr + 16 * s2);
        }

#pragma unroll
        for (int kc = 0; kc < 4; kc++) {
            const int pb = kc & 1;
            if (kc < 3) {
                const int nb2 = (kc + 1) & 1;
#pragma unroll
                for (int i = 0; i < 4; i++)
                    ldsm_x4(fa[nb2][i], sA + aRowB + i * 2048 + xa[kc + 1]);
#pragma unroll
                for (int jp = 0; jp < 4; jp++)
                    ldsm_x4(fb[nb2][jp], sB + bRowB + jp * 2048 + xb[kc + 1]);
            }
#pragma unroll
            for (int i = 0; i < 4; i++)
#pragma unroll
                for (int j = 0; j < 8; j++)
                    mma_f16(acc[i][j], fa[pb][i], &fb[pb][j >> 1][(j & 1) * 2]);
        }

        MBARRIER_ARRIVE(sbr + 16 * s + 8);

        if (++s == NST)  { s = 0;  fph ^= 1; }
        if (++s2 == NST) { s2 = 0; eph ^= 1; }
    }

#pragma unroll
    for (int i = 0; i < 4; i++) {
        int gm0 = bm + m0 + i * 16 + r;
#pragma unroll
        for (int j = 0; j < 8; j++) {
            int gn = bn + n0 + j * 8 + 2 * c;
            if (gn >= N) continue;
            float b0 = 0.f, b1 = 0.f;
            if (BIAS) {
                b0 = __half2float(__ldg(&bias[gn]));
                b1 = __half2float(__ldg(&bias[gn + 1]));
            }
            float4 v = acc[i][j];
            float x0 = v.x + b0, x1 = v.y + b1;
            float y0 = v.z + b0, y1 = v.w + b1;
            if (RELU) {
                x0 = fmaxf(x0, 0.f); x1 = fmaxf(x1, 0.f);
                y0 = fmaxf(y0, 0.f); y1 = fmaxf(y1, 0.f);
            }
            if (gm0 < M) {
                CT* p = &C[(size_t)gm0 * ldc + gn];
                if (sizeof(CT) == 2) *(half2*)p = __floats2half2_rn(x0, x1);
                else                 *(float2*)p = make_float2(x0, x1);
            }
            if (gm0 + 8 < M) {
                CT* p = &C[(size_t)(gm0 + 8) * ldc + gn];
                if (sizeof(CT) == 2) *(half2*)p = __floats2half2_rn(y0, y1);
                else                 *(float2*)p = make_float2(y0, y1);
            }
        }
    }
}

// ============================ mega kernel ===================================

__global__ __launch_bounds__(128, 2)
void mega(const __grid_constant__ CUtensorMap mA0, const __grid_constant__ CUtensorMap mB0,
          const __grid_constant__ CUtensorMap mA1, const __grid_constant__ CUtensorMap mB1,
          const __grid_constant__ CUtensorMap mA2, const __grid_constant__ CUtensorMap mB2,
          const __grid_constant__ CUtensorMap mA3, const __grid_constant__ CUtensorMap mB3,
          float* __restrict__ out)
{
    extern __shared__ uint32_t smu[];
    const int id  = blockIdx.x;
    const int tid = threadIdx.x;

    if (id < G0_CTAS) {
        // ---- seg0: Vf = V1h @ V2T^T (row-tiles low->high so cA fills early)
        int by = id / 46, bx = id % 46;
        gemm_body<false, false, __half>(smu, &mA0, &mB0, nullptr, g_Vf,
                                        SIZE_N, SIZE_N, K_PAD / 64, SIZE_N, bx, by);
        __syncthreads();
        if (tid == 0) {
            __threadfence();
            if (by < 12) red_rel(&g_cA);
            if (by < 34) red_rel(&g_cB);
            red_rel(&g_cC);
        }
    } else if (id < G0_CTAS + L1_CTAS) {
        // ---- seg1: h1 = relu(xh @ W1^T + b1); needs Vf rows < 1536
        int q = id - G0_CTAS;
        if (tid == 0) { spinc(&g_cA, TGT_A); FENCE_PROXY_ASYNC(); }
        __syncthreads();
        gemm_body<true, true, __half>(smu, &mA1, &mB1, g_Vf + OFF_B1, g_h1,
                                      BATCH, D_H, D_IN / 64, D_H, q & 31, q >> 5);
        __syncthreads();
        if (tid == 0) { __threadfence(); red_rel(&g_c1); }
    } else if (id < G0_CTAS + L1_CTAS + L2_CTAS) {
        // ---- seg2: h2 = relu(h1 @ W2^T + b2); needs Vf rows < 4352 + all h1
        int q = id - (G0_CTAS + L1_CTAS);
        if (tid == 0) { spinc(&g_cB, TGT_B); spinc(&g_c1, L1_CTAS); FENCE_PROXY_ASYNC(); }
        __syncthreads();
        gemm_body<true, true, __half>(smu, &mA2, &mB2, g_Vf + OFF_B2, g_h2,
                                      BATCH, D_H, D_H / 64, D_H, q & 31, q >> 5);
        __syncthreads();
        if (tid == 0) { __threadfence(); red_rel(&g_c2); }
    } else {
        // ---- seg3: out = h2 @ W3^T + b3; needs all Vf + all h2
        int q = id - (G0_CTAS + L1_CTAS + L2_CTAS);
        if (tid == 0) { spinc(&g_cC, G0_CTAS); spinc(&g_c2, L2_CTAS); FENCE_PROXY_ASYNC(); }
        __syncthreads();
        gemm_body<true, false, float>(smu, &mA3, &mB3, g_Vf + OFF_B3, out,
                                      BATCH, D_OUT, D_H / 64, D_OUT, q & 15, q >> 4);
    }
}

// ============================ prep kernels ==================================

__global__ void zero_counters_kernel() {
    g_cA = 0; g_cB = 0; g_cC = 0; g_c1 = 0; g_c2 = 0;
}

__global__ void tohalf_pad_kernel(const float* __restrict__ src, __half* __restrict__ dst,
                                  int rows, int cols, int dstride)
{
    const int pitchp = dstride >> 1;
    int totalp = rows * pitchp;
    for (int i = blockIdx.x * blockDim.x + threadIdx.x; i < totalp; i += gridDim.x * blockDim.x) {
        int rr = i / pitchp, p = i - rr * pitchp;
        int cc = p * 2;
        float v0 = (cc < cols)     ? src[(size_t)rr * cols + cc]     : 0.f;
        float v1 = (cc + 1 < cols) ? src[(size_t)rr * cols + cc + 1] : 0.f;
        *(half2*)&dst[(size_t)rr * dstride + cc] = __floats2half2_rn(v0, v1);
    }
}

__global__ void transpose_half_kernel(const float* __restrict__ src, __half* __restrict__ dst)
{
    __shared__ float t[32][33];
    int nb = blockIdx.x * 32;
    int kb = blockIdx.y * 32;
    int x = threadIdx.x, y = threadIdx.y;   // 32 x 8
#pragma unroll
    for (int yy = y; yy < 32; yy += 8) {
        int k = kb + yy, n = nb + x;
        float v = 0.0f;
        if (k < SIZE_M && n < SIZE_N) v = src[(size_t)k * SIZE_N + n];
        t[yy][x] = v;
    }
    __syncthreads();
    if (x < 16) {
#pragma unroll
        for (int yy = y; yy < 32; yy += 8) {
            int n = nb + yy, k2 = kb + 2 * x;
            if (n < SIZE_N && k2 < K_PAD) {
                half2 h = __floats2half2_rn(t[2 * x][yy], t[2 * x + 1][yy]);
                *(half2*)&dst[(size_t)n * K_PAD + k2] = h;
            }
        }
    }
}

// ============================ host side =====================================

typedef CUresult (*tmap_encode_fn)(
    CUtensorMap*, CUtensorMapDataType, cuuint32_t, void*,
    const cuuint64_t*, const cuuint64_t*, const cuuint32_t*, const cuuint32_t*,
    CUtensorMapInterleave, CUtensorMapSwizzle, CUtensorMapL2promotion, CUtensorMapFloatOOBfill);

static void make_map(CUtensorMap* m, void* ptr, uint64_t k_elems, uint64_t rows,
                     uint64_t stride_bytes)
{
    static tmap_encode_fn enc = nullptr;
    if (!enc) {
        cudaDriverEntryPointQueryResult qr;
        cudaGetDriverEntryPointByVersion("cuTensorMapEncodeTiled", (void**)&enc,
                                         12000, cudaEnableDefault, &qr);
    }
    cuuint64_t dims[2]    = {k_elems, rows};
    cuuint64_t strides[1] = {stride_bytes};
    cuuint32_t box[2]     = {64, 128};
    cuuint32_t es[2]      = {1, 1};
    enc(m, CU_TENSOR_MAP_DATA_TYPE_FLOAT16, 2, ptr, dims, strides, box, es,
        CU_TENSOR_MAP_INTERLEAVE_NONE, CU_TENSOR_MAP_SWIZZLE_128B,
        CU_TENSOR_MAP_L2_PROMOTION_L2_128B, CU_TENSOR_MAP_FLOAT_OOB_FILL_NONE);
}

extern "C" void kernel_launch(void* const* d_in, const int* in_sizes, int n_in,
                              void* d_out, int out_size)
{
    const float* x  = (const float*)d_in[0];   // [4096, 2048]
    const float* V1 = (const float*)d_in[1];   // [5794, 2897]
    const float* V2 = (const float*)d_in[2];   // [2897, 5794]
    float* out = (float*)d_out;                // [4096, 2048]

    __half *V1h, *V2T, *xh, *Vf, *h1, *h2;
    cudaGetSymbolAddress((void**)&V1h, g_V1h);
    cudaGetSymbolAddress((void**)&V2T, g_V2T);
    cudaGetSymbolAddress((void**)&xh,  g_xh);
    cudaGetSymbolAddress((void**)&Vf,  g_Vf);
    cudaGetSymbolAddress((void**)&h1,  g_h1);
    cudaGetSymbolAddress((void**)&h2,  g_h2);

    zero_counters_kernel<<<1, 1>>>();
    tohalf_pad_kernel<<<2048, 256>>>(V1, V1h, SIZE_N, SIZE_M, K_PAD);
    tohalf_pad_kernel<<<1024, 256>>>(x, xh, BATCH, D_IN, D_IN);
    transpose_half_kernel<<<dim3((SIZE_N + 31) / 32, (K_PAD + 31) / 32), dim3(32, 8)>>>(V2, V2T);

    CUtensorMap mA0, mB0, mA1, mB1, mA2, mB2, mA3, mB3;
    make_map(&mA0, V1h,          K_PAD, SIZE_N, (uint64_t)K_PAD * 2);
    make_map(&mB0, V2T,          K_PAD, SIZE_N, (uint64_t)K_PAD * 2);
    make_map(&mA1, xh,           D_IN,  BATCH,  (uint64_t)D_IN * 2);
    make_map(&mB1, Vf + OFF_W1,  D_IN,  D_H,    (uint64_t)D_IN * 2);
    make_map(&mA2, h1,           D_H,   BATCH,  (uint64_t)D_H * 2);
    make_map(&mB2, Vf + OFF_W2,  D_H,   D_H,    (uint64_t)D_H * 2);
    make_map(&mA3, h2,           D_H,   BATCH,  (uint64_t)D_H * 2);
    make_map(&mB3, Vf + OFF_W3,  D_H,   D_OUT,  (uint64_t)D_H * 2);

    cudaFuncSetAttribute(mega, cudaFuncAttributeMaxDynamicSharedMemorySize, SMEM_REQ);

    mega<<<G0_CTAS + L1_CTAS + L2_CTAS + L3_CTAS, 128, SMEM_REQ>>>(
        mA0, mB0, mA1, mB1, mA2, mB2, mA3, mB3, out);
}

// round 12
// speedup vs baseline: 2.6867x; 1.0677x over previous
#include <cuda_runtime.h>
#include <cuda.h>
#include <cuda_fp16.h>
#include <cstdint>

// ---------------------------------------------------------------------------
// FeatherNet, single mega-launch, per-row-block dependency counters:
//   seg0: Vf = V1@V2 (2116)  seg1: h1 (1024)  seg2: h2 (1024)  seg3: out (512)
//   seg2(by) waits only the 32 seg1 CTAs of its row block (g_c1r[by]);
//   seg3(by) waits only the 32 seg2 CTAs of its row block (g_c2r[by]) + all Vf.
// GEMM body: TMA + mbarrier ring + ldmatrix + mma.sync fp16 (R10).
// Prep kernels rewritten bandwidth-clean.
// ---------------------------------------------------------------------------

#define SIZE_N 5794
#define SIZE_M 2897
#define K_PAD  2944        // 46 * 64
#define BATCH  4096
#define D_IN   2048
#define D_H    4096
#define D_OUT  2048

#define OFF_W1 0
#define OFF_B1 8388608
#define OFF_W2 8392704
#define OFF_B2 25169920
#define OFF_W3 25174016
#define OFF_B3 33562624

#define G0_CTAS 2116       // 46 x 46
#define L1_CTAS 1024       // 32 x 32
#define L2_CTAS 1024
#define L3_CTAS 512        // 32 by x 16 bx
#define TGT_A   552        // 12 Vf row-tiles x 46 (covers W1+b1)
#define TGT_B   1564       // 34 Vf row-tiles x 46 (covers W2+b2)

__device__ __align__(256) __half g_V1h[(size_t)SIZE_N * K_PAD];
__device__ __align__(256) __half g_V2T[(size_t)SIZE_N * K_PAD];
__device__ __align__(256) __half g_xh [(size_t)BATCH * D_IN];
__device__ __align__(256) __half g_Vf [(size_t)SIZE_N * SIZE_N];
__device__ __align__(256) __half g_h1 [(size_t)BATCH * D_H];
__device__ __align__(256) __half g_h2 [(size_t)BATCH * D_H];

__device__ uint32_t g_cA, g_cB, g_cC;
__device__ uint32_t g_c1r[32], g_c2r[32];

// ============================ PTX helpers ===================================

__device__ __forceinline__ uint32_t smem_u32(const void* p) {
    uint32_t a;
    asm("{ .reg .u64 t; cvta.to.shared.u64 t, %1; cvt.u32.u64 %0, t; }"
        : "=r"(a) : "l"(p));
    return a;
}

#define MBARRIER_INIT(addr, cnt) \
    asm volatile("mbarrier.init.shared.b64 [%0], %1;" \
                 :: "r"((uint32_t)(addr)), "r"((uint32_t)(cnt)) : "memory")

#define MBARRIER_EXPECT_TX(addr, bytes) \
    asm volatile("mbarrier.arrive.expect_tx.shared.b64 _, [%0], %1;" \
                 :: "r"((uint32_t)(addr)), "r"((uint32_t)(bytes)) : "memory")

#define MBARRIER_ARRIVE(addr) \
    asm volatile("mbarrier.arrive.shared.b64 _, [%0];" \
                 :: "r"((uint32_t)(addr)) : "memory")

#define MBARRIER_WAIT_PARITY(addr, par) do {                                         \
    uint32_t _m = (uint32_t)(addr); uint32_t _p = (uint32_t)(par); uint32_t _d;      \
    asm volatile("{\n\t.reg .pred p;\n\t"                                            \
        "mbarrier.try_wait.parity.acquire.cta.shared::cta.b64 p, [%1], %2;\n\t"      \
        "selp.b32 %0, 1, 0, p;\n\t}"                                                 \
        : "=r"(_d) : "r"(_m), "r"(_p) : "memory");                                   \
    if (!_d) {                                                                       \
        asm volatile("{\n\t.reg .pred P1;\n\t"                                       \
            "WL_%=:\n\t"                                                             \
            "mbarrier.try_wait.parity.acquire.cta.shared::cta.b64 P1, [%0], %1, 0x989680;\n\t" \
            "@P1 bra.uni WD_%=;\n\t"                                                 \
            "bra.uni WL_%=;\n\t"                                                     \
            "WD_%=:\n\t}"                                                            \
            :: "r"(_m), "r"(_p) : "memory");                                         \
    }                                                                                \
} while (0)

__device__ __forceinline__ void tma2d(uint32_t dst, const CUtensorMap* m,
                                      int cx, int cy, uint32_t bar) {
    asm volatile(
        "cp.async.bulk.tensor.2d.shared::cta.global.tile.mbarrier::complete_tx::bytes "
        "[%0], [%1, {%2, %3}], [%4];"
        :: "r"(dst), "l"(m), "r"(cx), "r"(cy), "r"(bar) : "memory");
}

__device__ __forceinline__ void mma_f16(float4& d, const uint32_t* a, const uint32_t* b) {
    asm volatile(
        "mma.sync.aligned.m16n8k16.row.col.f32.f16.f16.f32 "
        "{%0,%1,%2,%3}, {%4,%5,%6,%7}, {%8,%9}, {%0,%1,%2,%3};"
        : "+f"(d.x), "+f"(d.y), "+f"(d.z), "+f"(d.w)
        : "r"(a[0]), "r"(a[1]), "r"(a[2]), "r"(a[3]), "r"(b[0]), "r"(b[1]));
}

__device__ __forceinline__ void ldsm_x4(uint32_t* r, uint32_t addr) {
    asm volatile("ldmatrix.sync.aligned.m8n8.x4.shared.b16 {%0,%1,%2,%3}, [%4];"
                 : "=r"(r[0]), "=r"(r[1]), "=r"(r[2]), "=r"(r[3]) : "r"(addr));
}

__device__ __forceinline__ uint32_t ld_acq(const uint32_t* p) {
    uint32_t v;
    asm volatile("ld.acquire.gpu.u32 %0, [%1];" : "=r"(v) : "l"(p) : "memory");
    return v;
}
__device__ __forceinline__ void red_rel(uint32_t* p) {
    asm volatile("red.release.gpu.add.u32 [%0], 1;" :: "l"(p) : "memory");
}
__device__ __forceinline__ void spinc(const uint32_t* p, uint32_t tgt) {
    while (ld_acq(p) < tgt) __nanosleep(128);
}
#define FENCE_PROXY_ASYNC() asm volatile("fence.proxy.async;" ::: "memory")

// ============================ GEMM body =====================================

#define NST 3
#define STAGE_BYTES 32768
#define SMEM_REQ 99392

template<bool BIAS, bool RELU, typename CT>
__device__ __forceinline__ void gemm_body(
    uint32_t* smu,
    const CUtensorMap* tmA, const CUtensorMap* tmB,
    const __half* __restrict__ bias, CT* __restrict__ C,
    int M, int N, int T, int ldc, int bx, int by)
{
    const uint32_t sbr = smem_u32(smu);
    const uint32_t st0 = (sbr + 48 + 1023) & ~1023u;

    const int tid = threadIdx.x;
    const int wid = tid >> 5;
    const int lid = tid & 31;
    const int r   = lid >> 2;
    const int c   = lid & 3;
    const int bm  = by * 128;
    const int bn  = bx * 128;
    const int m0  = (wid & 1) * 64;
    const int n0  = (wid >> 1) * 64;

    if (tid == 0) {
#pragma unroll
        for (int s = 0; s < NST; s++) {
            MBARRIER_INIT(sbr + 16 * s, 1);
            MBARRIER_INIT(sbr + 16 * s + 8, 128);
        }
    }
    __syncthreads();

    const int e    = lid & 7;
    const uint32_t aRowB = (uint32_t)(m0 + ((lid >> 3) & 1) * 8 + e) * 128;
    const uint32_t bRowB = (uint32_t)(n0 + (lid >> 4) * 8 + e) * 128;
    uint32_t xa[4], xb[4];
#pragma unroll
    for (int kc = 0; kc < 4; kc++) {
        xa[kc] = (uint32_t)((((2 * kc + (lid >> 4)) ^ e) & 7) * 16);
        xb[kc] = (uint32_t)((((2 * kc + ((lid >> 3) & 1)) ^ e) & 7) * 16);
    }

    float4 acc[4][8];
#pragma unroll
    for (int i = 0; i < 4; i++)
#pragma unroll
        for (int j = 0; j < 8; j++) acc[i][j] = make_float4(0.f, 0.f, 0.f, 0.f);

    if (tid == 0) {
        int npro = T < 2 ? T : 2;
        for (int p = 0; p < npro; p++) {
            MBARRIER_EXPECT_TX(sbr + 16 * p, STAGE_BYTES);
            tma2d(st0 + p * STAGE_BYTES,         tmA, p * 64, bm, sbr + 16 * p);
            tma2d(st0 + p * STAGE_BYTES + 16384, tmB, p * 64, bn, sbr + 16 * p);
        }
    }

    uint32_t fa[2][4][4], fb[2][4][4];

    int s = 0, fph = 0;
    int s2 = 2, eph = 1;
    for (int t = 0; t < T; t++) {
        MBARRIER_WAIT_PARITY(sbr + 16 * s, fph);

        const uint32_t sA = st0 + (uint32_t)s * STAGE_BYTES;
        const uint32_t sB = sA + 16384;

        ldsm_x4(fa[0][0], sA + aRowB + 0 * 2048 + xa[0]);
#pragma unroll
        for (int jp = 0; jp < 4; jp++) ldsm_x4(fb[0][jp], sB + bRowB + jp * 2048 + xb[0]);
#pragma unroll
        for (int i = 1; i < 4; i++)   ldsm_x4(fa[0][i], sA + aRowB + i * 2048 + xa[0]);

        if (tid == 0 && t + 2 < T) {
            MBARRIER_WAIT_PARITY(sbr + 16 * s2 + 8, eph);
            MBARRIER_EXPECT_TX(sbr + 16 * s2, STAGE_BYTES);
            uint32_t dA = st0 + (uint32_t)s2 * STAGE_BYTES;
            tma2d(dA,         tmA, (t + 2) * 64, bm, sbr + 16 * s2);
            tma2d(dA + 16384, tmB, (t + 2) * 64, bn, sbr + 16 * s2);
        }

#pragma unroll
        for (int kc = 0; kc < 4; kc++) {
            const int pb = kc & 1;
            if (kc < 3) {
                const int nb2 = (kc + 1) & 1;
#pragma unroll
                for (int i = 0; i < 4; i++)
                    ldsm_x4(fa[nb2][i], sA + aRowB + i * 2048 + xa[kc + 1]);
#pragma unroll
                for (int jp = 0; jp < 4; jp++)
                    ldsm_x4(fb[nb2][jp], sB + bRowB + jp * 2048 + xb[kc + 1]);
            }
#pragma unroll
            for (int i = 0; i < 4; i++)
#pragma unroll
                for (int j = 0; j < 8; j++)
                    mma_f16(acc[i][j], fa[pb][i], &fb[pb][j >> 1][(j & 1) * 2]);
        }

        MBARRIER_ARRIVE(sbr + 16 * s + 8);

        if (++s == NST)  { s = 0;  fph ^= 1; }
        if (++s2 == NST) { s2 = 0; eph ^= 1; }
    }

#pragma unroll
    for (int i = 0; i < 4; i++) {
        int gm0 = bm + m0 + i * 16 + r;
#pragma unroll
        for (int j = 0; j < 8; j++) {
            int gn = bn + n0 + j * 8 + 2 * c;
            if (gn >= N) continue;
            float b0 = 0.f, b1 = 0.f;
            if (BIAS) {
                b0 = __half2float(__ldg(&bias[gn]));
                b1 = __half2float(__ldg(&bias[gn + 1]));
            }
            float4 v = acc[i][j];
            float x0 = v.x + b0, x1 = v.y + b1;
            float y0 = v.z + b0, y1 = v.w + b1;
            if (RELU) {
                x0 = fmaxf(x0, 0.f); x1 = fmaxf(x1, 0.f);
                y0 = fmaxf(y0, 0.f); y1 = fmaxf(y1, 0.f);
            }
            if (gm0 < M) {
                CT* p = &C[(size_t)gm0 * ldc + gn];
                if (sizeof(CT) == 2) *(half2*)p = __floats2half2_rn(x0, x1);
                else                 *(float2*)p = make_float2(x0, x1);
            }
            if (gm0 + 8 < M) {
                CT* p = &C[(size_t)(gm0 + 8) * ldc + gn];
                if (sizeof(CT) == 2) *(half2*)p = __floats2half2_rn(y0, y1);
                else                 *(float2*)p = make_float2(y0, y1);
            }
        }
    }
}

// ============================ mega kernel ===================================

__global__ __launch_bounds__(128, 2)
void mega(const __grid_constant__ CUtensorMap mA0, const __grid_constant__ CUtensorMap mB0,
          const __grid_constant__ CUtensorMap mA1, const __grid_constant__ CUtensorMap mB1,
          const __grid_constant__ CUtensorMap mA2, const __grid_constant__ CUtensorMap mB2,
          const __grid_constant__ CUtensorMap mA3, const __grid_constant__ CUtensorMap mB3,
          float* __restrict__ out)
{
    extern __shared__ uint32_t smu[];
    const int id  = blockIdx.x;
    const int tid = threadIdx.x;

    if (id < G0_CTAS) {
        // ---- seg0: Vf = V1h @ V2T^T
        int by = id / 46, bx = id % 46;
        gemm_body<false, false, __half>(smu, &mA0, &mB0, nullptr, g_Vf,
                                        SIZE_N, SIZE_N, K_PAD / 64, SIZE_N, bx, by);
        __syncthreads();
        if (tid == 0) {
            __threadfence();
            if (by < 12) red_rel(&g_cA);
            if (by < 34) red_rel(&g_cB);
            red_rel(&g_cC);
        }
    } else if (id < G0_CTAS + L1_CTAS) {
        // ---- seg1: h1 = relu(xh @ W1^T + b1); needs Vf row-tiles 0..11
        int q = id - G0_CTAS;
        if (tid == 0) { spinc(&g_cA, TGT_A); FENCE_PROXY_ASYNC(); }
        __syncthreads();
        gemm_body<true, true, __half>(smu, &mA1, &mB1, g_Vf + OFF_B1, g_h1,
                                      BATCH, D_H, D_IN / 64, D_H, q & 31, q >> 5);
        __syncthreads();
        if (tid == 0) { __threadfence(); red_rel(&g_c1r[q >> 5]); }
    } else if (id < G0_CTAS + L1_CTAS + L2_CTAS) {
        // ---- seg2: h2 = relu(h1 @ W2^T + b2); needs Vf tiles 0..33 +
        //      only the 32 h1-CTAs of its own row block
        int q = id - (G0_CTAS + L1_CTAS);
        if (tid == 0) {
            spinc(&g_cB, TGT_B);
            spinc(&g_c1r[q >> 5], 32);
            FENCE_PROXY_ASYNC();
        }
        __syncthreads();
        gemm_body<true, true, __half>(smu, &mA2, &mB2, g_Vf + OFF_B2, g_h2,
                                      BATCH, D_H, D_H / 64, D_H, q & 31, q >> 5);
        __syncthreads();
        if (tid == 0) { __threadfence(); red_rel(&g_c2r[q >> 5]); }
    } else {
        // ---- seg3: out = h2 W3^T + b3; needs all Vf + its h2 row block
        int q = id - (G0_CTAS + L1_CTAS + L2_CTAS);
        if (tid == 0) {
            spinc(&g_cC, G0_CTAS);
            spinc(&g_c2r[q >> 4], 32);
            FENCE_PROXY_ASYNC();
        }
        __syncthreads();
        gemm_body<true, false, float>(smu, &mA3, &mB3, g_Vf + OFF_B3, out,
                                      BATCH, D_OUT, D_H / 64, D_OUT, q & 15, q >> 4);
    }
}

// ============================ prep kernels ==================================

__global__ void zero_counters_kernel() {
    int t = threadIdx.x;
    if (t == 0) { g_cA = 0; g_cB = 0; g_cC = 0; }
    if (t < 32) { g_c1r[t] = 0; g_c2r[t] = 0; }
}

// V1 [SIZE_N x SIZE_M] f32 -> V1h [SIZE_N x K_PAD] f16 (row per block, no div)
__global__ void tohalf_pad_row(const float* __restrict__ src, __half* __restrict__ dst)
{
    const int row = blockIdx.x;
    const float* s = src + (size_t)row * SIZE_M;
    __half* d = dst + (size_t)row * K_PAD;
    for (int p = threadIdx.x; p < K_PAD / 2; p += 256) {
        int cc = 2 * p;
        float v0 = (cc < SIZE_M)     ? s[cc]     : 0.f;
        float v1 = (cc + 1 < SIZE_M) ? s[cc + 1] : 0.f;
        *(half2*)&d[cc] = __floats2half2_rn(v0, v1);
    }
}

// x [BATCH x D_IN] f32 -> f16, fully vectorized (8 elems/thread)
__global__ void tohalf_vec(const float4* __restrict__ src, uint4* __restrict__ dst, int n8)
{
    int i = blockIdx.x * blockDim.x + threadIdx.x;
    if (i < n8) {
        float4 a = src[2 * i], b = src[2 * i + 1];
        half2 h0 = __floats2half2_rn(a.x, a.y), h1 = __floats2half2_rn(a.z, a.w);
        half2 h2 = __floats2half2_rn(b.x, b.y), h3 = __floats2half2_rn(b.z, b.w);
        uint4 o;
        o.x = *(uint32_t*)&h0; o.y = *(uint32_t*)&h1;
        o.z = *(uint32_t*)&h2; o.w = *(uint32_t*)&h3;
        dst[i] = o;
    }
}

// V2 [SIZE_M x SIZE_N] f32 -> V2T [SIZE_N x K_PAD] f16 (32x32 tiles, 256 thr,
// all lanes active both phases, conflict-free half2 phase 2)
__global__ void transpose_half2(const float* __restrict__ src, __half* __restrict__ dst)
{
    __shared__ float t[32][33];
    const int nb = blockIdx.x * 32;
    const int kb = blockIdx.y * 32;
    const int tid = threadIdx.x;   // 256
#pragma unroll
    for (int i = 0; i < 4; i++) {
        int idx = tid + i * 256;
        int kk = idx >> 5, nn = idx & 31;
        int k = kb + kk, n = nb + nn;
        float v = 0.f;
        if (k < SIZE_M && n < SIZE_N) v = src[(size_t)k * SIZE_N + n];
        t[kk][nn] = v;
    }
    __syncthreads();
#pragma unroll
    for (int i = 0; i < 2; i++) {
        int idx = tid + i * 256;
        int nn = idx >> 4, j = idx & 15;
        int n = nb + nn;
        if (n < SIZE_N) {
            half2 h = __floats2half2_rn(t[2 * j][nn], t[2 * j + 1][nn]);
            *(half2*)&dst[(size_t)n * K_PAD + kb + 2 * j] = h;
        }
    }
}

// ============================ host side =====================================

typedef CUresult (*tmap_encode_fn)(
    CUtensorMap*, CUtensorMapDataType, cuuint32_t, void*,
    const cuuint64_t*, const cuuint64_t*, const cuuint32_t*, const cuuint32_t*,
    CUtensorMapInterleave, CUtensorMapSwizzle, CUtensorMapL2promotion, CUtensorMapFloatOOBfill);

static void make_map(CUtensorMap* m, void* ptr, uint64_t k_elems, uint64_t rows,
                     uint64_t stride_bytes)
{
    static tmap_encode_fn enc = nullptr;
    if (!enc) {
        cudaDriverEntryPointQueryResult qr;
        cudaGetDriverEntryPointByVersion("cuTensorMapEncodeTiled", (void**)&enc,
                                         12000, cudaEnableDefault, &qr);
    }
    cuuint64_t dims[2]    = {k_elems, rows};
    cuuint64_t strides[1] = {stride_bytes};
    cuuint32_t box[2]     = {64, 128};
    cuuint32_t es[2]      = {1, 1};
    enc(m, CU_TENSOR_MAP_DATA_TYPE_FLOAT16, 2, ptr, dims, strides, box, es,
        CU_TENSOR_MAP_INTERLEAVE_NONE, CU_TENSOR_MAP_SWIZZLE_128B,
        CU_TENSOR_MAP_L2_PROMOTION_L2_128B, CU_TENSOR_MAP_FLOAT_OOB_FILL_NONE);
}

extern "C" void kernel_launch(void* const* d_in, const int* in_sizes, int n_in,
                              void* d_out, int out_size)
{
    const float* x  = (const float*)d_in[0];   // [4096, 2048]
    const float* V1 = (const float*)d_in[1];   // [5794, 2897]
    const float* V2 = (const float*)d_in[2];   // [2897, 5794]
    float* out = (float*)d_out;                // [4096, 2048]

    __half *V1h, *V2T, *xh, *Vf, *h1, *h2;
    cudaGetSymbolAddress((void**)&V1h, g_V1h);
    cudaGetSymbolAddress((void**)&V2T, g_V2T);
    cudaGetSymbolAddress((void**)&xh,  g_xh);
    cudaGetSymbolAddress((void**)&Vf,  g_Vf);
    cudaGetSymbolAddress((void**)&h1,  g_h1);
    cudaGetSymbolAddress((void**)&h2,  g_h2);

    zero_counters_kernel<<<1, 32>>>();
    tohalf_pad_row<<<SIZE_N, 256>>>(V1, V1h);
    tohalf_vec<<<(BATCH * D_IN / 8 + 255) / 256, 256>>>(
        (const float4*)x, (uint4*)xh, BATCH * D_IN / 8);
    transpose_half2<<<dim3((SIZE_N + 31) / 32, K_PAD / 32), 256>>>(V2, V2T);

    CUtensorMap mA0, mB0, mA1, mB1, mA2, mB2, mA3, mB3;
    make_map(&mA0, V1h,          K_PAD, SIZE_N, (uint64_t)K_PAD * 2);
    make_map(&mB0, V2T,          K_PAD, SIZE_N, (uint64_t)K_PAD * 2);
    make_map(&mA1, xh,           D_IN,  BATCH,  (uint64_t)D_IN * 2);
    make_map(&mB1, Vf + OFF_W1,  D_IN,  D_H,    (uint64_t)D_IN * 2);
    make_map(&mA2, h1,           D_H,   BATCH,  (uint64_t)D_H * 2);
    make_map(&mB2, Vf + OFF_W2,  D_H,   D_H,    (uint64_t)D_H * 2);
    make_map(&mA3, h2,           D_H,   BATCH,  (uint64_t)D_H * 2);
    make_map(&mB3, Vf + OFF_W3,  D_H,   D_OUT,  (uint64_t)D_H * 2);

    cudaFuncSetAttribute(mega, cudaFuncAttributeMaxDynamicSharedMemorySize, SMEM_REQ);

    mega<<<G0_CTAS + L1_CTAS + L2_CTAS + L3_CTAS, 128, SMEM_REQ>>>(
        mA0, mB0, mA1, mB1, mA2, mB2, mA3, mB3, out);
}

// round 13
// speedup vs baseline: 2.7082x; 1.0080x over previous
#include <cuda_runtime.h>
#include <cuda.h>
#include <cuda_fp16.h>
#include <cstdint>

// ---------------------------------------------------------------------------
// FeatherNet, single mega-launch, per-row-block dependency counters.
// R13: (1) cross-stage fragment pipelining — the full[s+1] wait and next
//      stage's kc0 ldmatrix run in the kc3 slot, overlapping MMAs, so the
//      stage-top ramp is gone; (2) all prep fused into ONE kernel.
//   seg0: Vf = V1@V2 (2116)  seg1: h1 (1024)  seg2: h2 (1024)  seg3: out (512)
// ---------------------------------------------------------------------------

#define SIZE_N 5794
#define SIZE_M 2897
#define K_PAD  2944        // 46 * 64
#define BATCH  4096
#define D_IN   2048
#define D_H    4096
#define D_OUT  2048

#define OFF_W1 0
#define OFF_B1 8388608
#define OFF_W2 8392704
#define OFF_B2 25169920
#define OFF_W3 25174016
#define OFF_B3 33562624

#define G0_CTAS 2116       // 46 x 46
#define L1_CTAS 1024       // 32 x 32
#define L2_CTAS 1024
#define L3_CTAS 512        // 32 by x 16 bx
#define TGT_A   552        // 12 Vf row-tiles x 46 (covers W1+b1)
#define TGT_B   1564       // 34 Vf row-tiles x 46 (covers W2+b2)

// prep grid segmentation
#define TRN_NB    182            // ceil(5794/32)
#define TRN_TILES (TRN_NB * (K_PAD / 32))   // 182*92 = 16744
#define XCONV_BLK (BATCH * D_IN / 8 / 256)  // 4096

__device__ __align__(256) __half g_V1h[(size_t)SIZE_N * K_PAD];
__device__ __align__(256) __half g_V2T[(size_t)SIZE_N * K_PAD];
__device__ __align__(256) __half g_xh [(size_t)BATCH * D_IN];
__device__ __align__(256) __half g_Vf [(size_t)SIZE_N * SIZE_N];
__device__ __align__(256) __half g_h1 [(size_t)BATCH * D_H];
__device__ __align__(256) __half g_h2 [(size_t)BATCH * D_H];

__device__ uint32_t g_cA, g_cB, g_cC;
__device__ uint32_t g_c1r[32], g_c2r[32];

// ============================ PTX helpers ===================================

__device__ __forceinline__ uint32_t smem_u32(const void* p) {
    uint32_t a;
    asm("{ .reg .u64 t; cvta.to.shared.u64 t, %1; cvt.u32.u64 %0, t; }"
        : "=r"(a) : "l"(p));
    return a;
}

#define MBARRIER_INIT(addr, cnt) \
    asm volatile("mbarrier.init.shared.b64 [%0], %1;" \
                 :: "r"((uint32_t)(addr)), "r"((uint32_t)(cnt)) : "memory")

#define MBARRIER_EXPECT_TX(addr, bytes) \
    asm volatile("mbarrier.arrive.expect_tx.shared.b64 _, [%0], %1;" \
                 :: "r"((uint32_t)(addr)), "r"((uint32_t)(bytes)) : "memory")

#define MBARRIER_ARRIVE(addr) \
    asm volatile("mbarrier.arrive.shared.b64 _, [%0];" \
                 :: "r"((uint32_t)(addr)) : "memory")

#define MBARRIER_WAIT_PARITY(addr, par) do {                                         \
    uint32_t _m = (uint32_t)(addr); uint32_t _p = (uint32_t)(par); uint32_t _d;      \
    asm volatile("{\n\t.reg .pred p;\n\t"                                            \
        "mbarrier.try_wait.parity.acquire.cta.shared::cta.b64 p, [%1], %2;\n\t"      \
        "selp.b32 %0, 1, 0, p;\n\t}"                                                 \
        : "=r"(_d) : "r"(_m), "r"(_p) : "memory");                                   \
    if (!_d) {                                                                       \
        asm volatile("{\n\t.reg .pred P1;\n\t"                                       \
            "WL_%=:\n\t"                                                             \
            "mbarrier.try_wait.parity.acquire.cta.shared::cta.b64 P1, [%0], %1, 0x989680;\n\t" \
            "@P1 bra.uni WD_%=;\n\t"                                                 \
            "bra.uni WL_%=;\n\t"                                                     \
            "WD_%=:\n\t}"                                                            \
            :: "r"(_m), "r"(_p) : "memory");                                         \
    }                                                                                \
} while (0)

__device__ __forceinline__ void tma2d(uint32_t dst, const CUtensorMap* m,
                                      int cx, int cy, uint32_t bar) {
    asm volatile(
        "cp.async.bulk.tensor.2d.shared::cta.global.tile.mbarrier::complete_tx::bytes "
        "[%0], [%1, {%2, %3}], [%4];"
        :: "r"(dst), "l"(m), "r"(cx), "r"(cy), "r"(bar) : "memory");
}

__device__ __forceinline__ void mma_f16(float4& d, const uint32_t* a, const uint32_t* b) {
    asm volatile(
        "mma.sync.aligned.m16n8k16.row.col.f32.f16.f16.f32 "
        "{%0,%1,%2,%3}, {%4,%5,%6,%7}, {%8,%9}, {%0,%1,%2,%3};"
        : "+f"(d.x), "+f"(d.y), "+f"(d.z), "+f"(d.w)
        : "r"(a[0]), "r"(a[1]), "r"(a[2]), "r"(a[3]), "r"(b[0]), "r"(b[1]));
}

__device__ __forceinline__ void ldsm_x4(uint32_t* r, uint32_t addr) {
    asm volatile("ldmatrix.sync.aligned.m8n8.x4.shared.b16 {%0,%1,%2,%3}, [%4];"
                 : "=r"(r[0]), "=r"(r[1]), "=r"(r[2]), "=r"(r[3]) : "r"(addr));
}

__device__ __forceinline__ uint32_t ld_acq(const uint32_t* p) {
    uint32_t v;
    asm volatile("ld.acquire.gpu.u32 %0, [%1];" : "=r"(v) : "l"(p) : "memory");
    return v;
}
__device__ __forceinline__ void red_rel(uint32_t* p) {
    asm volatile("red.release.gpu.add.u32 [%0], 1;" :: "l"(p) : "memory");
}
__device__ __forceinline__ void spinc(const uint32_t* p, uint32_t tgt) {
    while (ld_acq(p) < tgt) __nanosleep(128);
}
#define FENCE_PROXY_ASYNC() asm volatile("fence.proxy.async;" ::: "memory")

// ============================ GEMM body =====================================

#define NST 3
#define STAGE_BYTES 32768
#define SMEM_REQ 99392

template<bool BIAS, bool RELU, typename CT>
__device__ __forceinline__ void gemm_body(
    uint32_t* smu,
    const CUtensorMap* tmA, const CUtensorMap* tmB,
    const __half* __restrict__ bias, CT* __restrict__ C,
    int M, int N, int T, int ldc, int bx, int by)
{
    const uint32_t sbr = smem_u32(smu);
    const uint32_t st0 = (sbr + 48 + 1023) & ~1023u;

    const int tid = threadIdx.x;
    const int wid = tid >> 5;
    const int lid = tid & 31;
    const int r   = lid >> 2;
    const int c   = lid & 3;
    const int bm  = by * 128;
    const int bn  = bx * 128;
    const int m0  = (wid & 1) * 64;
    const int n0  = (wid >> 1) * 64;

    if (tid == 0) {
#pragma unroll
        for (int s = 0; s < NST; s++) {
            MBARRIER_INIT(sbr + 16 * s, 1);
            MBARRIER_INIT(sbr + 16 * s + 8, 128);
        }
    }
    __syncthreads();

    const int e    = lid & 7;
    const uint32_t aRowB = (uint32_t)(m0 + ((lid >> 3) & 1) * 8 + e) * 128;
    const uint32_t bRowB = (uint32_t)(n0 + (lid >> 4) * 8 + e) * 128;
    uint32_t xa[4], xb[4];
#pragma unroll
    for (int kc = 0; kc < 4; kc++) {
        xa[kc] = (uint32_t)((((2 * kc + (lid >> 4)) ^ e) & 7) * 16);
        xb[kc] = (uint32_t)((((2 * kc + ((lid >> 3) & 1)) ^ e) & 7) * 16);
    }

    float4 acc[4][8];
#pragma unroll
    for (int i = 0; i < 4; i++)
#pragma unroll
        for (int j = 0; j < 8; j++) acc[i][j] = make_float4(0.f, 0.f, 0.f, 0.f);

    if (tid == 0) {
        int npro = T < 2 ? T : 2;
        for (int p = 0; p < npro; p++) {
            MBARRIER_EXPECT_TX(sbr + 16 * p, STAGE_BYTES);
            tma2d(st0 + p * STAGE_BYTES,         tmA, p * 64, bm, sbr + 16 * p);
            tma2d(st0 + p * STAGE_BYTES + 16384, tmB, p * 64, bn, sbr + 16 * p);
        }
    }

    uint32_t fa[2][4][4], fb[2][4][4];

    int s = 0, fph = 0;
    int s2 = 2, eph = 1;

    // ---- prologue: consume full[0], load kc0 fragments into buffer 0 ------
    MBARRIER_WAIT_PARITY(sbr + 0, 0);
    {
        const uint32_t sA = st0, sB = st0 + 16384;
        ldsm_x4(fa[0][0], sA + aRowB + xa[0]);
#pragma unroll
        for (int jp = 0; jp < 4; jp++) ldsm_x4(fb[0][jp], sB + bRowB + jp * 2048 + xb[0]);
#pragma unroll
        for (int i = 1; i < 4; i++)   ldsm_x4(fa[0][i], sA + aRowB + i * 2048 + xa[0]);
    }

    for (int t = 0; t < T; t++) {
        const uint32_t sA = st0 + (uint32_t)s * STAGE_BYTES;
        const uint32_t sB = sA + 16384;

        if (tid == 0 && t + 2 < T) {
            MBARRIER_WAIT_PARITY(sbr + 16 * s2 + 8, eph);
            MBARRIER_EXPECT_TX(sbr + 16 * s2, STAGE_BYTES);
            uint32_t dA = st0 + (uint32_t)s2 * STAGE_BYTES;
            tma2d(dA,         tmA, (t + 2) * 64, bm, sbr + 16 * s2);
            tma2d(dA + 16384, tmB, (t + 2) * 64, bn, sbr + 16 * s2);
        }

#pragma unroll
        for (int kc = 0; kc < 4; kc++) {
            const int pb = kc & 1, nb2 = pb ^ 1;
            if (kc < 3) {
                // prefetch kc+1 of current stage
                ldsm_x4(fa[nb2][0], sA + aRowB + xa[kc + 1]);
#pragma unroll
                for (int jp = 0; jp < 4; jp++)
                    ldsm_x4(fb[nb2][jp], sB + bRowB + jp * 2048 + xb[kc + 1]);
#pragma unroll
                for (int i = 1; i < 4; i++)
                    ldsm_x4(fa[nb2][i], sA + aRowB + i * 2048 + xa[kc + 1]);
            } else if (t + 1 < T) {
                // cross-stage: wait next stage's full, prefetch its kc0
                const int sn  = (s + 1 == NST) ? 0 : s + 1;
                const int fpn = (s + 1 == NST) ? (fph ^ 1) : fph;
                MBARRIER_WAIT_PARITY(sbr + 16 * sn, fpn);
                const uint32_t nA = st0 + (uint32_t)sn * STAGE_BYTES;
                const uint32_t nB = nA + 16384;
                ldsm_x4(fa[nb2][0], nA + aRowB + xa[0]);
#pragma unroll
                for (int jp = 0; jp < 4; jp++)
                    ldsm_x4(fb[nb2][jp], nB + bRowB + jp * 2048 + xb[0]);
#pragma unroll
                for (int i = 1; i < 4; i++)
                    ldsm_x4(fa[nb2][i], nA + aRowB + i * 2048 + xa[0]);
            }
#pragma unroll
            for (int i = 0; i < 4; i++)
#pragma unroll
                for (int j = 0; j < 8; j++)
                    mma_f16(acc[i][j], fa[pb][i], &fb[pb][j >> 1][(j & 1) * 2]);
        }

        MBARRIER_ARRIVE(sbr + 16 * s + 8);

        if (++s == NST)  { s = 0;  fph ^= 1; }
        if (++s2 == NST) { s2 = 0; eph ^= 1; }
    }

#pragma unroll
    for (int i = 0; i < 4; i++) {
        int gm0 = bm + m0 + i * 16 + r;
#pragma unroll
        for (int j = 0; j < 8; j++) {
            int gn = bn + n0 + j * 8 + 2 * c;
            if (gn >= N) continue;
            float b0 = 0.f, b1 = 0.f;
            if (BIAS) {
                b0 = __half2float(__ldg(&bias[gn]));
                b1 = __half2float(__ldg(&bias[gn + 1]));
            }
            float4 v = acc[i][j];
            float x0 = v.x + b0, x1 = v.y + b1;
            float y0 = v.z + b0, y1 = v.w + b1;
            if (RELU) {
                x0 = fmaxf(x0, 0.f); x1 = fmaxf(x1, 0.f);
                y0 = fmaxf(y0, 0.f); y1 = fmaxf(y1, 0.f);
            }
            if (gm0 < M) {
                CT* p = &C[(size_t)gm0 * ldc + gn];
                if (sizeof(CT) == 2) *(half2*)p = __floats2half2_rn(x0, x1);
                else                 *(float2*)p = make_float2(x0, x1);
            }
            if (gm0 + 8 < M) {
                CT* p = &C[(size_t)(gm0 + 8) * ldc + gn];
                if (sizeof(CT) == 2) *(half2*)p = __floats2half2_rn(y0, y1);
                else                 *(float2*)p = make_float2(y0, y1);
            }
        }
    }
}

// ============================ mega kernel ===================================

__global__ __launch_bounds__(128, 2)
void mega(const __grid_constant__ CUtensorMap mA0, const __grid_constant__ CUtensorMap mB0,
          const __grid_constant__ CUtensorMap mA1, const __grid_constant__ CUtensorMap mB1,
          const __grid_constant__ CUtensorMap mA2, const __grid_constant__ CUtensorMap mB2,
          const __grid_constant__ CUtensorMap mA3, const __grid_constant__ CUtensorMap mB3,
          float* __restrict__ out)
{
    extern __shared__ uint32_t smu[];
    const int id  = blockIdx.x;
    const int tid = threadIdx.x;

    if (id < G0_CTAS) {
        int by = id / 46, bx = id % 46;
        gemm_body<false, false, __half>(smu, &mA0, &mB0, nullptr, g_Vf,
                                        SIZE_N, SIZE_N, K_PAD / 64, SIZE_N, bx, by);
        __syncthreads();
        if (tid == 0) {
            __threadfence();
            if (by < 12) red_rel(&g_cA);
            if (by < 34) red_rel(&g_cB);
            red_rel(&g_cC);
        }
    } else if (id < G0_CTAS + L1_CTAS) {
        int q = id - G0_CTAS;
        if (tid == 0) { spinc(&g_cA, TGT_A); FENCE_PROXY_ASYNC(); }
        __syncthreads();
        gemm_body<true, true, __half>(smu, &mA1, &mB1, g_Vf + OFF_B1, g_h1,
                                      BATCH, D_H, D_IN / 64, D_H, q & 31, q >> 5);
        __syncthreads();
        if (tid == 0) { __threadfence(); red_rel(&g_c1r[q >> 5]); }
    } else if (id < G0_CTAS + L1_CTAS + L2_CTAS) {
        int q = id - (G0_CTAS + L1_CTAS);
        if (tid == 0) {
            spinc(&g_cB, TGT_B);
            spinc(&g_c1r[q >> 5], 32);
            FENCE_PROXY_ASYNC();
        }
        __syncthreads();
        gemm_body<true, true, __half>(smu, &mA2, &mB2, g_Vf + OFF_B2, g_h2,
                                      BATCH, D_H, D_H / 64, D_H, q & 31, q >> 5);
        __syncthreads();
        if (tid == 0) { __threadfence(); red_rel(&g_c2r[q >> 5]); }
    } else {
        int q = id - (G0_CTAS + L1_CTAS + L2_CTAS);
        if (tid == 0) {
            spinc(&g_cC, G0_CTAS);
            spinc(&g_c2r[q >> 4], 32);
            FENCE_PROXY_ASYNC();
        }
        __syncthreads();
        gemm_body<true, false, float>(smu, &mA3, &mB3, g_Vf + OFF_B3, out,
                                      BATCH, D_OUT, D_H / 64, D_OUT, q & 15, q >> 4);
    }
}

// ============================ fused prep ====================================

__global__ void prep_all(const float* __restrict__ V1, const float* __restrict__ V2,
                         const float* __restrict__ x)
{
    const int id  = blockIdx.x;
    const int tid = threadIdx.x;

    if (id == 0 && tid < 33) {     // zero dependency counters
        if (tid == 32) { g_cA = 0; g_cB = 0; g_cC = 0; }
        else           { g_c1r[tid] = 0; g_c2r[tid] = 0; }
    }

    if (id < SIZE_N) {
        // V1 row conversion: [SIZE_M] f32 -> [K_PAD] f16, zero-padded
        const float* s = V1 + (size_t)id * SIZE_M;
        __half* d = g_V1h + (size_t)id * K_PAD;
        for (int p = tid; p < K_PAD / 2; p += 256) {
            int cc = 2 * p;
            float v0 = (cc < SIZE_M)     ? s[cc]     : 0.f;
            float v1 = (cc + 1 < SIZE_M) ? s[cc + 1] : 0.f;
            *(half2*)&d[cc] = __floats2half2_rn(v0, v1);
        }
    } else if (id < SIZE_N + TRN_TILES) {
        // V2 transpose tile: 32x32, f32 -> f16
        int q  = id - SIZE_N;
        int nb = (q % TRN_NB) * 32;
        int kb = (q / TRN_NB) * 32;
        __shared__ float tt[32][33];
#pragma unroll
        for (int i = 0; i < 4; i++) {
            int idx = tid + i * 256;
            int kk = idx >> 5, nn = idx & 31;
            int k = kb + kk, n = nb + nn;
            float v = 0.f;
            if (k < SIZE_M && n < SIZE_N) v = V2[(size_t)k * SIZE_N + n];
            tt[kk][nn] = v;
        }
        __syncthreads();
#pragma unroll
        for (int i = 0; i < 2; i++) {
            int idx = tid + i * 256;
            int nn = idx >> 4, j = idx & 15;
            int n = nb + nn;
            if (n < SIZE_N) {
                half2 h = __floats2half2_rn(tt[2 * j][nn], tt[2 * j + 1][nn]);
                *(half2*)&g_V2T[(size_t)n * K_PAD + kb + 2 * j] = h;
            }
        }
    } else {
        // x conversion: 8 f32 -> 8 f16 per thread
        int q = id - (SIZE_N + TRN_TILES);
        int i = q * 256 + tid;
        const float4* s4 = (const float4*)x;
        float4 a = s4[2 * i], b = s4[2 * i + 1];
        half2 h0 = __floats2half2_rn(a.x, a.y), h1 = __floats2half2_rn(a.z, a.w);
        half2 h2 = __floats2half2_rn(b.x, b.y), h3 = __floats2half2_rn(b.z, b.w);
        uint4 o;
        o.x = *(uint32_t*)&h0; o.y = *(uint32_t*)&h1;
        o.z = *(uint32_t*)&h2; o.w = *(uint32_t*)&h3;
        ((uint4*)g_xh)[i] = o;
    }
}

// ============================ host side =====================================

typedef CUresult (*tmap_encode_fn)(
    CUtensorMap*, CUtensorMapDataType, cuuint32_t, void*,
    const cuuint64_t*, const cuuint64_t*, const cuuint32_t*, const cuuint32_t*,
    CUtensorMapInterleave, CUtensorMapSwizzle, CUtensorMapL2promotion, CUtensorMapFloatOOBfill);

static void make_map(CUtensorMap* m, void* ptr, uint64_t k_elems, uint64_t rows,
                     uint64_t stride_bytes)
{
    static tmap_encode_fn enc = nullptr;
    if (!enc) {
        cudaDriverEntryPointQueryResult qr;
        cudaGetDriverEntryPointByVersion("cuTensorMapEncodeTiled", (void**)&enc,
                                         12000, cudaEnableDefault, &qr);
    }
    cuuint64_t dims[2]    = {k_elems, rows};
    cuuint64_t strides[1] = {stride_bytes};
    cuuint32_t box[2]     = {64, 128};
    cuuint32_t es[2]      = {1, 1};
    enc(m, CU_TENSOR_MAP_DATA_TYPE_FLOAT16, 2, ptr, dims, strides, box, es,
        CU_TENSOR_MAP_INTERLEAVE_NONE, CU_TENSOR_MAP_SWIZZLE_128B,
        CU_TENSOR_MAP_L2_PROMOTION_L2_128B, CU_TENSOR_MAP_FLOAT_OOB_FILL_NONE);
}

extern "C" void kernel_launch(void* const* d_in, const int* in_sizes, int n_in,
                              void* d_out, int out_size)
{
    const float* x  = (const float*)d_in[0];   // [4096, 2048]
    const float* V1 = (const float*)d_in[1];   // [5794, 2897]
    const float* V2 = (const float*)d_in[2];   // [2897, 5794]
    float* out = (float*)d_out;                // [4096, 2048]

    __half *V1h, *V2T, *xh, *Vf, *h1, *h2;
    cudaGetSymbolAddress((void**)&V1h, g_V1h);
    cudaGetSymbolAddress((void**)&V2T, g_V2T);
    cudaGetSymbolAddress((void**)&xh,  g_xh);
    cudaGetSymbolAddress((void**)&Vf,  g_Vf);
    cudaGetSymbolAddress((void**)&h1,  g_h1);
    cudaGetSymbolAddress((void**)&h2,  g_h2);

    prep_all<<<SIZE_N + TRN_TILES + XCONV_BLK, 256>>>(V1, V2, x);

    CUtensorMap mA0, mB0, mA1, mB1, mA2, mB2, mA3, mB3;
    make_map(&mA0, V1h,          K_PAD, SIZE_N, (uint64_t)K_PAD * 2);
    make_map(&mB0, V2T,          K_PAD, SIZE_N, (uint64_t)K_PAD * 2);
    make_map(&mA1, xh,           D_IN,  BATCH,  (uint64_t)D_IN * 2);
    make_map(&mB1, Vf + OFF_W1,  D_IN,  D_H,    (uint64_t)D_IN * 2);
    make_map(&mA2, h1,           D_H,   BATCH,  (uint64_t)D_H * 2);
    make_map(&mB2, Vf + OFF_W2,  D_H,   D_H,    (uint64_t)D_H * 2);
    make_map(&mA3, h2,           D_H,   BATCH,  (uint64_t)D_H * 2);
    make_map(&mB3, Vf + OFF_W3,  D_H,   D_OUT,  (uint64_t)D_H * 2);

    cudaFuncSetAttribute(mega, cudaFuncAttributeMaxDynamicSharedMemorySize, SMEM_REQ);

    mega<<<G0_CTAS + L1_CTAS + L2_CTAS + L3_CTAS, 128, SMEM_REQ>>>(
        mA0, mB0, mA1, mB1, mA2, mB2, mA3, mB3, out);
}